// round 3
// baseline (speedup 1.0000x reference)
#include <cuda_runtime.h>

// Problem constants
#define BB   4
#define LL   4096
#define DD   256
#define TILE 128
#define KT   16
#define SPAD 132   // padded smem row (132 floats) to soften bank conflicts

// ---------------------------------------------------------------------------
// Scratch (device globals: allocation-free, harness-legal)
// ---------------------------------------------------------------------------
__device__ float g_qp[BB * LL * DD];               // projected Q  (16.8 MB)
__device__ float g_kp[BB * LL * DD];               // projected K
__device__ float g_vp[BB * LL * DD];               // projected V
__device__ float g_S[BB * LL * LL];                // scores (268 MB)
__device__ float g_c[BB * LL];                     // per-row  m + log(sumexp)

// ---------------------------------------------------------------------------
// Packed f32x2 helpers (Blackwell sm_100+: FFMA2 doubles fp32 FMA throughput)
// ---------------------------------------------------------------------------
__device__ __forceinline__ unsigned long long ffma2(unsigned long long a,
                                                    unsigned long long b,
                                                    unsigned long long c) {
    unsigned long long d;
    asm("fma.rn.f32x2 %0, %1, %2, %3;" : "=l"(d) : "l"(a), "l"(b), "l"(c));
    return d;
}
__device__ __forceinline__ unsigned long long pack2(float x, float y) {
    unsigned long long r;
    asm("mov.b64 %0, {%1, %2};" : "=l"(r) : "f"(x), "f"(y));
    return r;
}
__device__ __forceinline__ float2 unpack2(unsigned long long p) {
    float2 r;
    asm("mov.b64 {%0, %1}, %2;" : "=f"(r.x), "=f"(r.y) : "l"(p));
    return r;
}

// ---------------------------------------------------------------------------
// NT GEMM: C[M,N] = scale * (A[M,K] @ B[N,K]^T) (+ bias[N])
// Both operands K-contiguous (row-major [rows, K]).
// CTA tile 128x128, K-step 16, 256 threads, 8x8 register tile per thread,
// accumulators held as packed f32x2 pairs along N.
// Used for: projections (M=B*L, N=K=256) and scores (per batch via blockIdx.z).
// ---------------------------------------------------------------------------
__global__ void __launch_bounds__(256, 2)
gemm_nt(const float* __restrict__ A, const float* __restrict__ Bm,
        const float* __restrict__ bias, float* __restrict__ C,
        int K, int N, size_t sA, size_t sB, size_t sC, float scale)
{
    A  += (size_t)blockIdx.z * sA;
    Bm += (size_t)blockIdx.z * sB;
    C  += (size_t)blockIdx.z * sC;

    __shared__ __align__(16) float As[KT][SPAD];   // transposed: [k][m]
    __shared__ __align__(16) float Bs[KT][SPAD];   // transposed: [k][n]

    const int t    = threadIdx.x;
    const int m0   = blockIdx.y * TILE;
    const int n0   = blockIdx.x * TILE;
    const int warp = t >> 5, lane = t & 31;
    // warps: 2 along M x 4 along N; lanes: 8 along M x 4 along N
    const int tm = (warp & 1) * 64 + (lane & 7) * 8;
    const int tn = (warp >> 1) * 32 + (lane >> 3) * 8;

    unsigned long long acc[8][4];
#pragma unroll
    for (int i = 0; i < 8; i++)
#pragma unroll
        for (int j = 0; j < 4; j++) acc[i][j] = 0ull;

    for (int k0 = 0; k0 < K; k0 += KT) {
        // stage 128 rows x 16 k of each operand, transposing into smem
#pragma unroll
        for (int r = 0; r < 2; r++) {
            int idx = t + 256 * r;            // 512 slots = 128 rows x 4 float4
            int row = idx >> 2;
            int c4  = (idx & 3) * 4;
            float4 av = *(const float4*)(A  + (size_t)(m0 + row) * K + k0 + c4);
            float4 bv = *(const float4*)(Bm + (size_t)(n0 + row) * K + k0 + c4);
            As[c4 + 0][row] = av.x; As[c4 + 1][row] = av.y;
            As[c4 + 2][row] = av.z; As[c4 + 3][row] = av.w;
            Bs[c4 + 0][row] = bv.x; Bs[c4 + 1][row] = bv.y;
            Bs[c4 + 2][row] = bv.z; Bs[c4 + 3][row] = bv.w;
        }
        __syncthreads();
#pragma unroll
        for (int k = 0; k < KT; k++) {
            float4 a0 = *(const float4*)&As[k][tm];
            float4 a1 = *(const float4*)&As[k][tm + 4];
            ulonglong2 b0 = *(const ulonglong2*)&Bs[k][tn];
            ulonglong2 b1 = *(const ulonglong2*)&Bs[k][tn + 4];
            float aa[8] = {a0.x, a0.y, a0.z, a0.w, a1.x, a1.y, a1.z, a1.w};
#pragma unroll
            for (int i = 0; i < 8; i++) {
                unsigned long long ad = pack2(aa[i], aa[i]);
                acc[i][0] = ffma2(ad, b0.x, acc[i][0]);
                acc[i][1] = ffma2(ad, b0.y, acc[i][1]);
                acc[i][2] = ffma2(ad, b1.x, acc[i][2]);
                acc[i][3] = ffma2(ad, b1.y, acc[i][3]);
            }
        }
        __syncthreads();
    }

#pragma unroll
    for (int i = 0; i < 8; i++) {
        size_t rowoff = (size_t)(m0 + tm + i) * N;
#pragma unroll
        for (int jp = 0; jp < 4; jp++) {
            int col = n0 + tn + jp * 2;
            float2 vv = unpack2(acc[i][jp]);
            vv.x *= scale; vv.y *= scale;
            if (bias) { vv.x += bias[col]; vv.y += bias[col + 1]; }
            *(float2*)(C + rowoff + col) = vv;
        }
    }
}

// ---------------------------------------------------------------------------
// Row softmax stats: c[row] = max_j S[row,j] + log( sum_j exp(S[row,j]-max) )
// One 256-thread block per row (rows = B*L, each row = LL contiguous floats).
// ---------------------------------------------------------------------------
__global__ void __launch_bounds__(256)
rowstats(const float* __restrict__ S, float* __restrict__ c)
{
    const int row = blockIdx.x;                 // b*LL + i, S contiguous
    const float* Sr = S + (size_t)row * LL;
    const int t = threadIdx.x;

    float x[16];
    float m = -3.0e38f;
#pragma unroll
    for (int u = 0; u < 16; u++) {
        x[u] = Sr[t + 256 * u];
        m = fmaxf(m, x[u]);
    }
#pragma unroll
    for (int o = 16; o > 0; o >>= 1)
        m = fmaxf(m, __shfl_xor_sync(0xffffffffu, m, o));

    __shared__ float redm[8];
    __shared__ float redl[8];
    if ((t & 31) == 0) redm[t >> 5] = m;
    __syncthreads();
    m = redm[0];
#pragma unroll
    for (int w = 1; w < 8; w++) m = fmaxf(m, redm[w]);

    float l = 0.0f;
#pragma unroll
    for (int u = 0; u < 16; u++) l += expf(x[u] - m);
#pragma unroll
    for (int o = 16; o > 0; o >>= 1)
        l += __shfl_xor_sync(0xffffffffu, l, o);
    if ((t & 31) == 0) redl[t >> 5] = l;
    __syncthreads();
    if (t == 0) {
        float s = 0.0f;
#pragma unroll
        for (int w = 0; w < 8; w++) s += redl[w];
        c[row] = m + logf(s);
    }
}

// ---------------------------------------------------------------------------
// Output GEMM (TN): out[b,j,d] = sum_i exp(S[b,i,j]-c[b,i]) * V[b,i,d]
// Contraction over i (rows of both operands) -> no smem transpose needed,
// fully coalesced staging; exp applied while filling the P tile.
// ---------------------------------------------------------------------------
__global__ void __launch_bounds__(256, 2)
attn_out(const float* __restrict__ S, const float* __restrict__ V,
         const float* __restrict__ c, float* __restrict__ out)
{
    const int b = blockIdx.z;
    const float* Sb = S + (size_t)b * LL * LL;
    const float* Vb = V + (size_t)b * LL * DD;
    const float* cb = c + b * LL;
    float* Ob = out + (size_t)b * LL * DD;

    const int j0 = blockIdx.y * TILE;   // output row tile (key axis j)
    const int d0 = blockIdx.x * TILE;   // output col tile (feature axis d)

    __shared__ __align__(16) float Ps[KT][SPAD];   // [i_local][j]
    __shared__ __align__(16) float Vs[KT][SPAD];   // [i_local][d]

    const int t    = threadIdx.x;
    const int warp = t >> 5, lane = t & 31;
    const int tm = (warp & 1) * 64 + (lane & 7) * 8;   // j fragment
    const int tn = (warp >> 1) * 32 + (lane >> 3) * 8; // d fragment

    unsigned long long acc[8][4];
#pragma unroll
    for (int i = 0; i < 8; i++)
#pragma unroll
        for (int j = 0; j < 4; j++) acc[i][j] = 0ull;

    for (int i0 = 0; i0 < LL; i0 += KT) {
#pragma unroll
        for (int r = 0; r < 2; r++) {
            int idx = t + 256 * r;           // 512 slots = 16 rows x 32 float4
            int kk = idx >> 5;
            int cc = (idx & 31) * 4;
            int irow = i0 + kk;
            float ci = cb[irow];
            float4 sv = *(const float4*)(Sb + (size_t)irow * LL + j0 + cc);
            float4 pv;
            pv.x = expf(sv.x - ci); pv.y = expf(sv.y - ci);
            pv.z = expf(sv.z - ci); pv.w = expf(sv.w - ci);
            *(float4*)&Ps[kk][cc] = pv;
            *(float4*)&Vs[kk][cc] = *(const float4*)(Vb + (size_t)irow * DD + d0 + cc);
        }
        __syncthreads();
#pragma unroll
        for (int k = 0; k < KT; k++) {
            float4 a0 = *(const float4*)&Ps[k][tm];
            float4 a1 = *(const float4*)&Ps[k][tm + 4];
            ulonglong2 b0 = *(const ulonglong2*)&Vs[k][tn];
            ulonglong2 b1 = *(const ulonglong2*)&Vs[k][tn + 4];
            float aa[8] = {a0.x, a0.y, a0.z, a0.w, a1.x, a1.y, a1.z, a1.w};
#pragma unroll
            for (int i = 0; i < 8; i++) {
                unsigned long long ad = pack2(aa[i], aa[i]);
                acc[i][0] = ffma2(ad, b0.x, acc[i][0]);
                acc[i][1] = ffma2(ad, b0.y, acc[i][1]);
                acc[i][2] = ffma2(ad, b1.x, acc[i][2]);
                acc[i][3] = ffma2(ad, b1.y, acc[i][3]);
            }
        }
        __syncthreads();
    }

#pragma unroll
    for (int i = 0; i < 8; i++) {
        size_t rowoff = (size_t)(j0 + tm + i) * DD;
#pragma unroll
        for (int jp = 0; jp < 4; jp++) {
            int col = d0 + tn + jp * 2;
            float2 vv = unpack2(acc[i][jp]);
            *(float2*)(Ob + rowoff + col) = vv;
        }
    }
}

// ---------------------------------------------------------------------------
// Launch: 6 kernels, default stream, graph-capturable, no allocations.
// Inputs (metadata order): q, k, v, Wq, bq, Wk, bk, Wv, bv
// ---------------------------------------------------------------------------
extern "C" void kernel_launch(void* const* d_in, const int* in_sizes, int n_in,
                              void* d_out, int out_size)
{
    const float* q  = (const float*)d_in[0];
    const float* k  = (const float*)d_in[1];
    const float* v  = (const float*)d_in[2];
    const float* Wq = (const float*)d_in[3];
    const float* bq = (const float*)d_in[4];
    const float* Wk = (const float*)d_in[5];
    const float* bk = (const float*)d_in[6];
    const float* Wv = (const float*)d_in[7];
    const float* bv = (const float*)d_in[8];
    float* out = (float*)d_out;

    float *gq, *gk, *gv, *gS, *gc;
    cudaGetSymbolAddress((void**)&gq, g_qp);
    cudaGetSymbolAddress((void**)&gk, g_kp);
    cudaGetSymbolAddress((void**)&gv, g_vp);
    cudaGetSymbolAddress((void**)&gS, g_S);
    cudaGetSymbolAddress((void**)&gc, g_c);

    dim3 thr(256);

    // 1) Projections: [B*L,256] @ [256,256]^T + bias
    dim3 gProj(DD / TILE, (BB * LL) / TILE, 1);
    gemm_nt<<<gProj, thr>>>(q, Wq, bq, gq, DD, DD, 0, 0, 0, 1.0f);
    gemm_nt<<<gProj, thr>>>(k, Wk, bk, gk, DD, DD, 0, 0, 0, 1.0f);
    gemm_nt<<<gProj, thr>>>(v, Wv, bv, gv, DD, DD, 0, 0, 0, 1.0f);

    // 2) Scores: per batch S = Q' K'^T / 16
    dim3 gScore(LL / TILE, LL / TILE, BB);
    gemm_nt<<<gScore, thr>>>(gq, gk, nullptr, gS, DD, LL,
                             (size_t)LL * DD, (size_t)LL * DD,
                             (size_t)LL * LL, 0.0625f);

    // 3) Per-query-row softmax stats
    rowstats<<<BB * LL, thr>>>(gS, gc);

    // 4) out = P^T V with on-the-fly P = exp(S - c)
    dim3 gOut(DD / TILE, LL / TILE, BB);
    attn_out<<<gOut, thr>>>(gS, gv, gc, out);
}

// round 5
// speedup vs baseline: 1.4908x; 1.4908x over previous
#include <cuda_runtime.h>
#include <cuda_fp16.h>
#include <cstdint>

#define BB   4
#define LL   4096
#define DD   256
#define TILE 128
#define KT   16
#define SPAD 132

// ---------------------------------------------------------------------------
// Device scratch (allocation-free)
// ---------------------------------------------------------------------------
__device__ __align__(256) __half g_qhi[BB * LL * DD];
__device__ __align__(256) __half g_qlo[BB * LL * DD];
__device__ __align__(256) __half g_khi[BB * LL * DD];
__device__ __align__(256) __half g_klo[BB * LL * DD];
__device__ __align__(256) float  g_vp [BB * LL * DD];
__device__ __align__(256) float  g_S  [(size_t)BB * LL * LL];
__device__ __align__(256) float  g_c  [BB * LL];
__device__ __align__(256) __half g_pthi[(size_t)BB * LL * LL];
__device__ __align__(256) __half g_ptlo[(size_t)BB * LL * LL];
__device__ __align__(256) __half g_vthi[BB * DD * LL];
__device__ __align__(256) __half g_vtlo[BB * DD * LL];

// ---------------------------------------------------------------------------
// fp32 -> fp16 two-term split (hi 11 bits, lo next ~11 -> ~2^-24 combined)
// ---------------------------------------------------------------------------
__device__ __forceinline__ void split_half(float x, __half& h, __half& l) {
    h = __float2half_rn(x);
    l = __float2half_rn(x - __half2float(h));
}

// ---------------------------------------------------------------------------
// Packed f32x2 helpers (projection GEMMs)
// ---------------------------------------------------------------------------
__device__ __forceinline__ unsigned long long ffma2(unsigned long long a,
                                                    unsigned long long b,
                                                    unsigned long long c) {
    unsigned long long d;
    asm("fma.rn.f32x2 %0, %1, %2, %3;" : "=l"(d) : "l"(a), "l"(b), "l"(c));
    return d;
}
__device__ __forceinline__ unsigned long long pack2(float x, float y) {
    unsigned long long r;
    asm("mov.b64 %0, {%1, %2};" : "=l"(r) : "f"(x), "f"(y));
    return r;
}
__device__ __forceinline__ float2 unpack2(unsigned long long p) {
    float2 r;
    asm("mov.b64 {%0, %1}, %2;" : "=f"(r.x), "=f"(r.y) : "l"(p));
    return r;
}

// ---------------------------------------------------------------------------
// Projection GEMM (FFMA2): C[M,256] = A[M,256] @ W[256,256]^T + bias.
// If OHi != null, writes fp16 split (hi/lo) instead of fp32 C.
// ---------------------------------------------------------------------------
__global__ void __launch_bounds__(256, 2)
gemm_nt(const float* __restrict__ A, const float* __restrict__ Bm,
        const float* __restrict__ bias, float* __restrict__ C,
        __half* __restrict__ OHi, __half* __restrict__ OLo,
        int K, int N)
{
    __shared__ __align__(16) float As[KT][SPAD];
    __shared__ __align__(16) float Bs[KT][SPAD];

    const int t    = threadIdx.x;
    const int m0   = blockIdx.y * TILE;
    const int n0   = blockIdx.x * TILE;
    const int warp = t >> 5, lane = t & 31;
    const int tm = (warp & 1) * 64 + (lane & 7) * 8;
    const int tn = (warp >> 1) * 32 + (lane >> 3) * 8;

    unsigned long long acc[8][4];
#pragma unroll
    for (int i = 0; i < 8; i++)
#pragma unroll
        for (int j = 0; j < 4; j++) acc[i][j] = 0ull;

    for (int k0 = 0; k0 < K; k0 += KT) {
#pragma unroll
        for (int r = 0; r < 2; r++) {
            int idx = t + 256 * r;
            int row = idx >> 2;
            int c4  = (idx & 3) * 4;
            float4 av = *(const float4*)(A  + (size_t)(m0 + row) * K + k0 + c4);
            float4 bv = *(const float4*)(Bm + (size_t)(n0 + row) * K + k0 + c4);
            As[c4 + 0][row] = av.x; As[c4 + 1][row] = av.y;
            As[c4 + 2][row] = av.z; As[c4 + 3][row] = av.w;
            Bs[c4 + 0][row] = bv.x; Bs[c4 + 1][row] = bv.y;
            Bs[c4 + 2][row] = bv.z; Bs[c4 + 3][row] = bv.w;
        }
        __syncthreads();
#pragma unroll
        for (int k = 0; k < KT; k++) {
            float4 a0 = *(const float4*)&As[k][tm];
            float4 a1 = *(const float4*)&As[k][tm + 4];
            ulonglong2 b0 = *(const ulonglong2*)&Bs[k][tn];
            ulonglong2 b1 = *(const ulonglong2*)&Bs[k][tn + 4];
            float aa[8] = {a0.x, a0.y, a0.z, a0.w, a1.x, a1.y, a1.z, a1.w};
#pragma unroll
            for (int i = 0; i < 8; i++) {
                unsigned long long ad = pack2(aa[i], aa[i]);
                acc[i][0] = ffma2(ad, b0.x, acc[i][0]);
                acc[i][1] = ffma2(ad, b0.y, acc[i][1]);
                acc[i][2] = ffma2(ad, b1.x, acc[i][2]);
                acc[i][3] = ffma2(ad, b1.y, acc[i][3]);
            }
        }
        __syncthreads();
    }

#pragma unroll
    for (int i = 0; i < 8; i++) {
        size_t rowoff = (size_t)(m0 + tm + i) * N;
#pragma unroll
        for (int jp = 0; jp < 4; jp++) {
            int col = n0 + tn + jp * 2;
            float2 vv = unpack2(acc[i][jp]);
            vv.x += bias[col];
            vv.y += bias[col + 1];
            if (OHi) {
                __half h0, l0, h1, l1;
                split_half(vv.x, h0, l0);
                split_half(vv.y, h1, l1);
                __half2 hh; hh.x = h0; hh.y = h1;
                __half2 ll; ll.x = l0; ll.y = l1;
                *(__half2*)(OHi + rowoff + col) = hh;
                *(__half2*)(OLo + rowoff + col) = ll;
            } else {
                *(float2*)(C + rowoff + col) = vv;
            }
        }
    }
}

// ---------------------------------------------------------------------------
// mma.sync m16n8k16 fp16 -> fp32 (sm_80+, legal on base sm_100)
// ---------------------------------------------------------------------------
__device__ __forceinline__ void mma16816(float* d, const uint32_t* a, const uint32_t* b) {
    asm volatile(
        "mma.sync.aligned.m16n8k16.row.col.f32.f16.f16.f32 "
        "{%0,%1,%2,%3}, {%4,%5,%6,%7}, {%8,%9}, {%0,%1,%2,%3};"
        : "+f"(d[0]), "+f"(d[1]), "+f"(d[2]), "+f"(d[3])
        : "r"(a[0]), "r"(a[1]), "r"(a[2]), "r"(a[3]), "r"(b[0]), "r"(b[1]));
}

// ---------------------------------------------------------------------------
// Split-fp16 NT GEMM on tensor cores (mma.sync):
//   C[128x128 tile] = scale * sum_k (Ahi+Alo)[m,k] * (Bhi+Blo)[n,k]
// 256 threads = 2(m) x 4(n) warps, warp tile 64x32, K-step 32.
// Smem rows padded to 40 halves (80B): fragment LDS.32 loads are
// bank-conflict-free (row i -> word offset 20*i mod 32, all distinct)
// and 16B staging stores stay aligned.
// ---------------------------------------------------------------------------
#define SROW 40

__global__ void __launch_bounds__(256)
mma_nt_split(const __half* __restrict__ Ahg, const __half* __restrict__ Alg,
             const __half* __restrict__ Bhg, const __half* __restrict__ Blg,
             float* __restrict__ C,
             int K, int ldA, int ldB, int ldC,
             size_t zA, size_t zB, size_t zC, float scale)
{
    __shared__ __half sAh[128][SROW];
    __shared__ __half sAl[128][SROW];
    __shared__ __half sBh[128][SROW];
    __shared__ __half sBl[128][SROW];

    const int t = threadIdx.x;
    const int wid = t >> 5, lane = t & 31;
    const int wm = wid >> 2;          // 0..1  -> m offset 64*wm
    const int wn = wid & 3;           // 0..3  -> n offset 32*wn
    const int fr = lane >> 2;         // fragment row within 8
    const int fc = (lane & 3) * 2;    // fragment k-pair column

    Ahg += (size_t)blockIdx.z * zA;  Alg += (size_t)blockIdx.z * zA;
    Bhg += (size_t)blockIdx.z * zB;  Blg += (size_t)blockIdx.z * zB;
    C   += (size_t)blockIdx.z * zC;
    const int m0 = blockIdx.y * 128;
    const int n0 = blockIdx.x * 128;

    float acc[4][4][4];
#pragma unroll
    for (int i = 0; i < 4; i++)
#pragma unroll
        for (int j = 0; j < 4; j++)
#pragma unroll
            for (int e = 0; e < 4; e++) acc[i][j][e] = 0.0f;

    const int srow = t >> 2;          // staging row (0..63) + 64*it
    const int sq   = (t & 3) * 8;     // staging quad (halves)

    for (int k0 = 0; k0 < K; k0 += 32) {
        // ---- stage 128x32 halves of each of the 4 operands ----
#pragma unroll
        for (int it = 0; it < 2; it++) {
            int row = srow + 64 * it;
            size_t ea = (size_t)(m0 + row) * ldA + k0 + sq;
            size_t eb = (size_t)(n0 + row) * ldB + k0 + sq;
            *(uint4*)&sAh[row][sq] = *(const uint4*)(Ahg + ea);
            *(uint4*)&sAl[row][sq] = *(const uint4*)(Alg + ea);
            *(uint4*)&sBh[row][sq] = *(const uint4*)(Bhg + eb);
            *(uint4*)&sBl[row][sq] = *(const uint4*)(Blg + eb);
        }
        __syncthreads();

        // ---- two k16 sub-steps ----
#pragma unroll
        for (int ks = 0; ks < 32; ks += 16) {
            uint32_t ah[4][4], al[4][4], bh[4][2], bl[4][2];
#pragma unroll
            for (int mt = 0; mt < 4; mt++) {
                int r = wm * 64 + mt * 16 + fr;
                ah[mt][0] = *(const uint32_t*)&sAh[r    ][fc + ks];
                ah[mt][1] = *(const uint32_t*)&sAh[r + 8][fc + ks];
                ah[mt][2] = *(const uint32_t*)&sAh[r    ][fc + ks + 8];
                ah[mt][3] = *(const uint32_t*)&sAh[r + 8][fc + ks + 8];
                al[mt][0] = *(const uint32_t*)&sAl[r    ][fc + ks];
                al[mt][1] = *(const uint32_t*)&sAl[r + 8][fc + ks];
                al[mt][2] = *(const uint32_t*)&sAl[r    ][fc + ks + 8];
                al[mt][3] = *(const uint32_t*)&sAl[r + 8][fc + ks + 8];
            }
#pragma unroll
            for (int nt = 0; nt < 4; nt++) {
                int r = wn * 32 + nt * 8 + fr;
                bh[nt][0] = *(const uint32_t*)&sBh[r][fc + ks];
                bh[nt][1] = *(const uint32_t*)&sBh[r][fc + ks + 8];
                bl[nt][0] = *(const uint32_t*)&sBl[r][fc + ks];
                bl[nt][1] = *(const uint32_t*)&sBl[r][fc + ks + 8];
            }
#pragma unroll
            for (int mt = 0; mt < 4; mt++)
#pragma unroll
                for (int nt = 0; nt < 4; nt++) {
                    mma16816(acc[mt][nt], ah[mt], bh[nt]);
                    mma16816(acc[mt][nt], ah[mt], bl[nt]);
                    mma16816(acc[mt][nt], al[mt], bh[nt]);
                }
        }
        __syncthreads();
    }

    // ---- epilogue ----
#pragma unroll
    for (int mt = 0; mt < 4; mt++) {
        int row = m0 + wm * 64 + mt * 16 + fr;
#pragma unroll
        for (int nt = 0; nt < 4; nt++) {
            int col = n0 + wn * 32 + nt * 8 + fc;
            float2 v0, v1;
            v0.x = acc[mt][nt][0] * scale;
            v0.y = acc[mt][nt][1] * scale;
            v1.x = acc[mt][nt][2] * scale;
            v1.y = acc[mt][nt][3] * scale;
            *(float2*)(C + (size_t)row * ldC + col)       = v0;
            *(float2*)(C + (size_t)(row + 8) * ldC + col) = v1;
        }
    }
}

// ---------------------------------------------------------------------------
// Row softmax stats: c[row] = max + log(sumexp)
// ---------------------------------------------------------------------------
__global__ void __launch_bounds__(256)
rowstats(const float* __restrict__ S, float* __restrict__ c)
{
    const int row = blockIdx.x;
    const float* Sr = S + (size_t)row * LL;
    const int t = threadIdx.x;

    float x[16];
    float m = -3.0e38f;
#pragma unroll
    for (int u = 0; u < 16; u++) {
        x[u] = Sr[t + 256 * u];
        m = fmaxf(m, x[u]);
    }
#pragma unroll
    for (int o = 16; o > 0; o >>= 1)
        m = fmaxf(m, __shfl_xor_sync(0xffffffffu, m, o));

    __shared__ float redm[8];
    __shared__ float redl[8];
    if ((t & 31) == 0) redm[t >> 5] = m;
    __syncthreads();
    m = redm[0];
#pragma unroll
    for (int w = 1; w < 8; w++) m = fmaxf(m, redm[w]);

    float l = 0.0f;
#pragma unroll
    for (int u = 0; u < 16; u++) l += expf(x[u] - m);
#pragma unroll
    for (int o = 16; o > 0; o >>= 1)
        l += __shfl_xor_sync(0xffffffffu, l, o);
    if ((t & 31) == 0) redl[t >> 5] = l;
    __syncthreads();
    if (t == 0) {
        float s = 0.0f;
#pragma unroll
        for (int w = 0; w < 8; w++) s += redl[w];
        c[row] = m + logf(s);
    }
}

// ---------------------------------------------------------------------------
// P^T build: Pt[b][j][i] = exp(S[b][i][j] - c[b,i]), fp16 hi/lo split.
// ---------------------------------------------------------------------------
__global__ void __launch_bounds__(256)
make_pt(const float* __restrict__ S, const float* __restrict__ c,
        __half* __restrict__ Phi, __half* __restrict__ Plo)
{
    const int b = blockIdx.z;
    const float* Sb = S + (size_t)b * LL * LL;
    const float* cb = c + b * LL;
    __shared__ float tile[32][33];
    const int tx = threadIdx.x, ty = threadIdx.y;   // 32 x 8
    const int j0 = blockIdx.x * 32, i0 = blockIdx.y * 32;

#pragma unroll
    for (int r = 0; r < 4; r++) {
        int i = i0 + ty + r * 8;
        float s = Sb[(size_t)i * LL + j0 + tx];
        tile[ty + r * 8][tx] = __expf(s - cb[i]);
    }
    __syncthreads();
    const size_t ob = (size_t)b * LL * LL;
#pragma unroll
    for (int r = 0; r < 4; r++) {
        int j = j0 + ty + r * 8;
        float pv = tile[tx][ty + r * 8];
        __half h, l;
        split_half(pv, h, l);
        size_t o = ob + (size_t)j * LL + i0 + tx;
        Phi[o] = h;
        Plo[o] = l;
    }
}

// ---------------------------------------------------------------------------
// V^T build: Vt[b][d][i] = split(Vp[b][i][d])
// ---------------------------------------------------------------------------
__global__ void __launch_bounds__(256)
v_split_t(const float* __restrict__ V,
          __half* __restrict__ Vhi, __half* __restrict__ Vlo)
{
    const int b = blockIdx.z;
    const float* Vb = V + (size_t)b * LL * DD;
    __shared__ float tile[32][33];
    const int tx = threadIdx.x, ty = threadIdx.y;   // 32 x 8
    const int d0 = blockIdx.x * 32, i0 = blockIdx.y * 32;

#pragma unroll
    for (int r = 0; r < 4; r++) {
        int i = i0 + ty + r * 8;
        tile[ty + r * 8][tx] = Vb[(size_t)i * DD + d0 + tx];
    }
    __syncthreads();
    const size_t ob = (size_t)b * DD * LL;
#pragma unroll
    for (int r = 0; r < 4; r++) {
        int d = d0 + ty + r * 8;
        float v = tile[tx][ty + r * 8];
        __half h, l;
        split_half(v, h, l);
        size_t o = ob + (size_t)d * LL + i0 + tx;
        Vhi[o] = h;
        Vlo[o] = l;
    }
}

// ---------------------------------------------------------------------------
// Launch
// ---------------------------------------------------------------------------
extern "C" void kernel_launch(void* const* d_in, const int* in_sizes, int n_in,
                              void* d_out, int out_size)
{
    const float* q  = (const float*)d_in[0];
    const float* k  = (const float*)d_in[1];
    const float* v  = (const float*)d_in[2];
    const float* Wq = (const float*)d_in[3];
    const float* bq = (const float*)d_in[4];
    const float* Wk = (const float*)d_in[5];
    const float* bk = (const float*)d_in[6];
    const float* Wv = (const float*)d_in[7];
    const float* bv = (const float*)d_in[8];
    float* out = (float*)d_out;

    __half *qhi, *qlo, *khi, *klo, *pthi, *ptlo, *vthi, *vtlo;
    float *vp, *S, *c;
    cudaGetSymbolAddress((void**)&qhi,  g_qhi);
    cudaGetSymbolAddress((void**)&qlo,  g_qlo);
    cudaGetSymbolAddress((void**)&khi,  g_khi);
    cudaGetSymbolAddress((void**)&klo,  g_klo);
    cudaGetSymbolAddress((void**)&vp,   g_vp);
    cudaGetSymbolAddress((void**)&S,    g_S);
    cudaGetSymbolAddress((void**)&c,    g_c);
    cudaGetSymbolAddress((void**)&pthi, g_pthi);
    cudaGetSymbolAddress((void**)&ptlo, g_ptlo);
    cudaGetSymbolAddress((void**)&vthi, g_vthi);
    cudaGetSymbolAddress((void**)&vtlo, g_vtlo);

    // 1) Projections (Q,K -> fp16 split; V -> fp32)
    dim3 gProj(DD / TILE, (BB * LL) / TILE, 1);
    gemm_nt<<<gProj, 256>>>(q, Wq, bq, nullptr, qhi, qlo, DD, DD);
    gemm_nt<<<gProj, 256>>>(k, Wk, bk, nullptr, khi, klo, DD, DD);
    gemm_nt<<<gProj, 256>>>(v, Wv, bv, vp, nullptr, nullptr, DD, DD);

    // 2) V^T split (K-major B operand for the output GEMM)
    v_split_t<<<dim3(DD / 32, LL / 32, BB), dim3(32, 8)>>>(vp, vthi, vtlo);

    // 3) Scores: S[b,i,j] = (Q' K'^T)/16 via split-fp16 mma.sync
    mma_nt_split<<<dim3(LL / 128, LL / 128, BB), 256>>>(
        qhi, qlo, khi, klo, S,
        DD, DD, DD, LL,
        (size_t)LL * DD, (size_t)LL * DD, (size_t)LL * LL, 0.0625f);

    // 4) Per-query-row logsumexp
    rowstats<<<BB * LL, 256>>>(S, c);

    // 5) Pt = exp(S - c)^T, fp16 split
    make_pt<<<dim3(LL / 32, LL / 32, BB), dim3(32, 8)>>>(S, c, pthi, ptlo);

    // 6) out[b,j,d] = sum_i Pt[b,j,i] * Vt[b,d,i] via split-fp16 mma.sync
    mma_nt_split<<<dim3(DD / 128, LL / 128, BB), 256>>>(
        pthi, ptlo, vthi, vtlo, out,
        LL, LL, LL, DD,
        (size_t)LL * LL, (size_t)DD * LL, (size_t)LL * DD, 1.0f);
}

// round 6
// speedup vs baseline: 1.7060x; 1.1444x over previous
#include <cuda_runtime.h>
#include <cuda_fp16.h>
#include <cstdint>

#define BB   4
#define LL   4096
#define DD   256
#define TILE 128
#define KT   16
#define SPAD 132

// ---------------------------------------------------------------------------
// Device scratch (allocation-free)
// ---------------------------------------------------------------------------
__device__ __align__(256) __half g_qhi[BB * LL * DD];
__device__ __align__(256) __half g_qlo[BB * LL * DD];
__device__ __align__(256) __half g_khi[BB * LL * DD];
__device__ __align__(256) __half g_klo[BB * LL * DD];
__device__ __align__(256) float  g_vp [BB * LL * DD];
__device__ __align__(256) float  g_S  [(size_t)BB * LL * LL];
__device__ __align__(256) float  g_c  [BB * LL];
__device__ __align__(256) __half g_pthi[(size_t)BB * LL * LL];
__device__ __align__(256) __half g_ptlo[(size_t)BB * LL * LL];
__device__ __align__(256) __half g_vthi[BB * DD * LL];
__device__ __align__(256) __half g_vtlo[BB * DD * LL];

// ---------------------------------------------------------------------------
// fp32 -> fp16 two-term split
// ---------------------------------------------------------------------------
__device__ __forceinline__ void split_half(float x, __half& h, __half& l) {
    h = __float2half_rn(x);
    l = __float2half_rn(x - __half2float(h));
}

// ---------------------------------------------------------------------------
// Packed f32x2 helpers (projection GEMMs)
// ---------------------------------------------------------------------------
__device__ __forceinline__ unsigned long long ffma2(unsigned long long a,
                                                    unsigned long long b,
                                                    unsigned long long c) {
    unsigned long long d;
    asm("fma.rn.f32x2 %0, %1, %2, %3;" : "=l"(d) : "l"(a), "l"(b), "l"(c));
    return d;
}
__device__ __forceinline__ unsigned long long pack2(float x, float y) {
    unsigned long long r;
    asm("mov.b64 %0, {%1, %2};" : "=l"(r) : "f"(x), "f"(y));
    return r;
}
__device__ __forceinline__ float2 unpack2(unsigned long long p) {
    float2 r;
    asm("mov.b64 {%0, %1}, %2;" : "=f"(r.x), "=f"(r.y) : "l"(p));
    return r;
}

// ---------------------------------------------------------------------------
// Projection GEMM (FFMA2): C[M,256] = A[M,256] @ W[256,256]^T + bias.
// If OHi != null, writes fp16 split (hi/lo) instead of fp32 C.
// ---------------------------------------------------------------------------
__global__ void __launch_bounds__(256, 2)
gemm_nt(const float* __restrict__ A, const float* __restrict__ Bm,
        const float* __restrict__ bias, float* __restrict__ C,
        __half* __restrict__ OHi, __half* __restrict__ OLo,
        int K, int N)
{
    __shared__ __align__(16) float As[KT][SPAD];
    __shared__ __align__(16) float Bs[KT][SPAD];

    const int t    = threadIdx.x;
    const int m0   = blockIdx.y * TILE;
    const int n0   = blockIdx.x * TILE;
    const int warp = t >> 5, lane = t & 31;
    const int tm = (warp & 1) * 64 + (lane & 7) * 8;
    const int tn = (warp >> 1) * 32 + (lane >> 3) * 8;

    unsigned long long acc[8][4];
#pragma unroll
    for (int i = 0; i < 8; i++)
#pragma unroll
        for (int j = 0; j < 4; j++) acc[i][j] = 0ull;

    for (int k0 = 0; k0 < K; k0 += KT) {
#pragma unroll
        for (int r = 0; r < 2; r++) {
            int idx = t + 256 * r;
            int row = idx >> 2;
            int c4  = (idx & 3) * 4;
            float4 av = *(const float4*)(A  + (size_t)(m0 + row) * K + k0 + c4);
            float4 bv = *(const float4*)(Bm + (size_t)(n0 + row) * K + k0 + c4);
            As[c4 + 0][row] = av.x; As[c4 + 1][row] = av.y;
            As[c4 + 2][row] = av.z; As[c4 + 3][row] = av.w;
            Bs[c4 + 0][row] = bv.x; Bs[c4 + 1][row] = bv.y;
            Bs[c4 + 2][row] = bv.z; Bs[c4 + 3][row] = bv.w;
        }
        __syncthreads();
#pragma unroll
        for (int k = 0; k < KT; k++) {
            float4 a0 = *(const float4*)&As[k][tm];
            float4 a1 = *(const float4*)&As[k][tm + 4];
            ulonglong2 b0 = *(const ulonglong2*)&Bs[k][tn];
            ulonglong2 b1 = *(const ulonglong2*)&Bs[k][tn + 4];
            float aa[8] = {a0.x, a0.y, a0.z, a0.w, a1.x, a1.y, a1.z, a1.w};
#pragma unroll
            for (int i = 0; i < 8; i++) {
                unsigned long long ad = pack2(aa[i], aa[i]);
                acc[i][0] = ffma2(ad, b0.x, acc[i][0]);
                acc[i][1] = ffma2(ad, b0.y, acc[i][1]);
                acc[i][2] = ffma2(ad, b1.x, acc[i][2]);
                acc[i][3] = ffma2(ad, b1.y, acc[i][3]);
            }
        }
        __syncthreads();
    }

#pragma unroll
    for (int i = 0; i < 8; i++) {
        size_t rowoff = (size_t)(m0 + tm + i) * N;
#pragma unroll
        for (int jp = 0; jp < 4; jp++) {
            int col = n0 + tn + jp * 2;
            float2 vv = unpack2(acc[i][jp]);
            vv.x += bias[col];
            vv.y += bias[col + 1];
            if (OHi) {
                __half h0, l0, h1, l1;
                split_half(vv.x, h0, l0);
                split_half(vv.y, h1, l1);
                __half2 hh; hh.x = h0; hh.y = h1;
                __half2 ll; ll.x = l0; ll.y = l1;
                *(__half2*)(OHi + rowoff + col) = hh;
                *(__half2*)(OLo + rowoff + col) = ll;
            } else {
                *(float2*)(C + rowoff + col) = vv;
            }
        }
    }
}

// ---------------------------------------------------------------------------
// mma.sync m16n8k16 fp16 -> fp32
// ---------------------------------------------------------------------------
__device__ __forceinline__ void mma16816(float* d, const uint32_t* a, const uint32_t* b) {
    asm volatile(
        "mma.sync.aligned.m16n8k16.row.col.f32.f16.f16.f32 "
        "{%0,%1,%2,%3}, {%4,%5,%6,%7}, {%8,%9}, {%0,%1,%2,%3};"
        : "+f"(d[0]), "+f"(d[1]), "+f"(d[2]), "+f"(d[3])
        : "r"(a[0]), "r"(a[1]), "r"(a[2]), "r"(a[3]), "r"(b[0]), "r"(b[1]));
}

__device__ __forceinline__ uint32_t smem_u32p(const void* p) {
    uint32_t a;
    asm("{ .reg .u64 t; cvta.to.shared.u64 t, %1; cvt.u32.u64 %0, t; }"
        : "=r"(a) : "l"(p));
    return a;
}
__device__ __forceinline__ void cp_async16(uint32_t saddr, const void* g) {
    asm volatile("cp.async.cg.shared.global [%0], [%1], 16;"
                 :: "r"(saddr), "l"(g) : "memory");
}
#define CP_COMMIT()  asm volatile("cp.async.commit_group;" ::: "memory")
#define CP_WAIT1()   asm volatile("cp.async.wait_group 1;" ::: "memory")

// ---------------------------------------------------------------------------
// Split-fp16 NT GEMM on tensor cores with cp.async double buffering:
//   C[128x128 tile] = scale * sum_k (Ahi+Alo)[m,k] * (Bhi+Blo)[n,k]
// 256 threads = 2(m) x 4(n) warps, warp tile 64x32, K-step 32.
// Smem rows = 40 halves (80B): conflict-free fragment LDS and aligned 16B
// staging. Two 40KB buffers in dynamic smem; chunk k+1 prefetched via
// cp.async while chunk k computes.
// ---------------------------------------------------------------------------
#define SROW   40
#define OPSZ   (128 * SROW * 2)     // 10240 B per operand tile
#define BUFSZ  (4 * OPSZ)           // 40960 B per buffer
#define MMA_DYN (2 * BUFSZ)         // 81920 B total

__global__ void __launch_bounds__(256)
mma_nt_split(const __half* __restrict__ Ahg, const __half* __restrict__ Alg,
             const __half* __restrict__ Bhg, const __half* __restrict__ Blg,
             float* __restrict__ C,
             int K, int ldA, int ldB, int ldC,
             size_t zA, size_t zB, size_t zC, float scale)
{
    extern __shared__ __align__(16) char dyn[];
    const uint32_t su = smem_u32p(dyn);

    const int t = threadIdx.x;
    const int wid = t >> 5, lane = t & 31;
    const int wm = wid >> 2;          // m offset 64*wm
    const int wn = wid & 3;           // n offset 32*wn
    const int fr = lane >> 2;
    const int fc = (lane & 3) * 2;

    Ahg += (size_t)blockIdx.z * zA;  Alg += (size_t)blockIdx.z * zA;
    Bhg += (size_t)blockIdx.z * zB;  Blg += (size_t)blockIdx.z * zB;
    C   += (size_t)blockIdx.z * zC;
    const int m0 = blockIdx.y * 128;
    const int n0 = blockIdx.x * 128;

    float acc[4][4][4];
#pragma unroll
    for (int i = 0; i < 4; i++)
#pragma unroll
        for (int j = 0; j < 4; j++)
#pragma unroll
            for (int e = 0; e < 4; e++) acc[i][j][e] = 0.0f;

    const int srow = t >> 2;          // staging row (0..63), +64 per iter
    const int sq   = (t & 3) * 8;     // staging halves offset

    // --- async stage of one 128x32 chunk of all 4 operands into buffer b ---
    auto stage = [&](int b, int k0) {
        const uint32_t base = su + b * BUFSZ;
#pragma unroll
        for (int it = 0; it < 2; it++) {
            int row = srow + 64 * it;
            uint32_t so = base + row * (SROW * 2) + sq * 2;
            size_t ea = (size_t)(m0 + row) * ldA + k0 + sq;
            size_t eb = (size_t)(n0 + row) * ldB + k0 + sq;
            cp_async16(so + 0 * OPSZ, Ahg + ea);
            cp_async16(so + 1 * OPSZ, Alg + ea);
            cp_async16(so + 2 * OPSZ, Bhg + eb);
            cp_async16(so + 3 * OPSZ, Blg + eb);
        }
    };

    const int nchunks = K >> 5;
    stage(0, 0);
    CP_COMMIT();

    for (int kc = 0; kc < nchunks; kc++) {
        if (kc + 1 < nchunks) stage((kc + 1) & 1, (kc + 1) << 5);
        CP_COMMIT();
        CP_WAIT1();               // buffer kc is complete
        __syncthreads();

        const char* p = dyn + (kc & 1) * BUFSZ;
        const __half (*sAh)[SROW] = (const __half (*)[SROW])(p + 0 * OPSZ);
        const __half (*sAl)[SROW] = (const __half (*)[SROW])(p + 1 * OPSZ);
        const __half (*sBh)[SROW] = (const __half (*)[SROW])(p + 2 * OPSZ);
        const __half (*sBl)[SROW] = (const __half (*)[SROW])(p + 3 * OPSZ);

#pragma unroll
        for (int ks = 0; ks < 32; ks += 16) {
            uint32_t ah[4][4], al[4][4], bh[4][2], bl[4][2];
#pragma unroll
            for (int mt = 0; mt < 4; mt++) {
                int r = wm * 64 + mt * 16 + fr;
                ah[mt][0] = *(const uint32_t*)&sAh[r    ][fc + ks];
                ah[mt][1] = *(const uint32_t*)&sAh[r + 8][fc + ks];
                ah[mt][2] = *(const uint32_t*)&sAh[r    ][fc + ks + 8];
                ah[mt][3] = *(const uint32_t*)&sAh[r + 8][fc + ks + 8];
                al[mt][0] = *(const uint32_t*)&sAl[r    ][fc + ks];
                al[mt][1] = *(const uint32_t*)&sAl[r + 8][fc + ks];
                al[mt][2] = *(const uint32_t*)&sAl[r    ][fc + ks + 8];
                al[mt][3] = *(const uint32_t*)&sAl[r + 8][fc + ks + 8];
            }
#pragma unroll
            for (int nt = 0; nt < 4; nt++) {
                int r = wn * 32 + nt * 8 + fr;
                bh[nt][0] = *(const uint32_t*)&sBh[r][fc + ks];
                bh[nt][1] = *(const uint32_t*)&sBh[r][fc + ks + 8];
                bl[nt][0] = *(const uint32_t*)&sBl[r][fc + ks];
                bl[nt][1] = *(const uint32_t*)&sBl[r][fc + ks + 8];
            }
#pragma unroll
            for (int mt = 0; mt < 4; mt++)
#pragma unroll
                for (int nt = 0; nt < 4; nt++) {
                    mma16816(acc[mt][nt], ah[mt], bh[nt]);
                    mma16816(acc[mt][nt], ah[mt], bl[nt]);
                    mma16816(acc[mt][nt], al[mt], bh[nt]);
                }
        }
        __syncthreads();          // all reads of buffer kc done before refill
    }

    // ---- epilogue ----
#pragma unroll
    for (int mt = 0; mt < 4; mt++) {
        int row = m0 + wm * 64 + mt * 16 + fr;
#pragma unroll
        for (int nt = 0; nt < 4; nt++) {
            int col = n0 + wn * 32 + nt * 8 + fc;
            float2 v0, v1;
            v0.x = acc[mt][nt][0] * scale;
            v0.y = acc[mt][nt][1] * scale;
            v1.x = acc[mt][nt][2] * scale;
            v1.y = acc[mt][nt][3] * scale;
            *(float2*)(C + (size_t)row * ldC + col)       = v0;
            *(float2*)(C + (size_t)(row + 8) * ldC + col) = v1;
        }
    }
}

// ---------------------------------------------------------------------------
// Row softmax stats: c[row] = max + log(sumexp)  (pure-bandwidth scan)
// ---------------------------------------------------------------------------
__global__ void __launch_bounds__(256)
rowstats(const float* __restrict__ S, float* __restrict__ c)
{
    const int row = blockIdx.x;
    const float* Sr = S + (size_t)row * LL;
    const int t = threadIdx.x;

    float x[16];
    float m = -3.0e38f;
#pragma unroll
    for (int u = 0; u < 16; u++) {
        x[u] = Sr[t + 256 * u];
        m = fmaxf(m, x[u]);
    }
#pragma unroll
    for (int o = 16; o > 0; o >>= 1)
        m = fmaxf(m, __shfl_xor_sync(0xffffffffu, m, o));

    __shared__ float redm[8];
    __shared__ float redl[8];
    if ((t & 31) == 0) redm[t >> 5] = m;
    __syncthreads();
    m = redm[0];
#pragma unroll
    for (int w = 1; w < 8; w++) m = fmaxf(m, redm[w]);

    float l = 0.0f;
#pragma unroll
    for (int u = 0; u < 16; u++) l += __expf(x[u] - m);
#pragma unroll
    for (int o = 16; o > 0; o >>= 1)
        l += __shfl_xor_sync(0xffffffffu, l, o);
    if ((t & 31) == 0) redl[t >> 5] = l;
    __syncthreads();
    if (t == 0) {
        float s = 0.0f;
#pragma unroll
        for (int w = 0; w < 8; w++) s += redl[w];
        c[row] = m + __logf(s);
    }
}

// ---------------------------------------------------------------------------
// P^T build: Pt[b][j][i] = exp(S[b][i][j] - c[b,i]), fp16 hi/lo split.
// ---------------------------------------------------------------------------
__global__ void __launch_bounds__(256)
make_pt(const float* __restrict__ S, const float* __restrict__ c,
        __half* __restrict__ Phi, __half* __restrict__ Plo)
{
    const int b = blockIdx.z;
    const float* Sb = S + (size_t)b * LL * LL;
    const float* cb = c + b * LL;
    __shared__ float tile[32][33];
    const int tx = threadIdx.x, ty = threadIdx.y;   // 32 x 8
    const int j0 = blockIdx.x * 32, i0 = blockIdx.y * 32;

#pragma unroll
    for (int r = 0; r < 4; r++) {
        int i = i0 + ty + r * 8;
        float s = Sb[(size_t)i * LL + j0 + tx];
        tile[ty + r * 8][tx] = __expf(s - cb[i]);
    }
    __syncthreads();
    const size_t ob = (size_t)b * LL * LL;
#pragma unroll
    for (int r = 0; r < 4; r++) {
        int j = j0 + ty + r * 8;
        float pv = tile[tx][ty + r * 8];
        __half h, l;
        split_half(pv, h, l);
        size_t o = ob + (size_t)j * LL + i0 + tx;
        Phi[o] = h;
        Plo[o] = l;
    }
}

// ---------------------------------------------------------------------------
// V^T build: Vt[b][d][i] = split(Vp[b][i][d])
// ---------------------------------------------------------------------------
__global__ void __launch_bounds__(256)
v_split_t(const float* __restrict__ V,
          __half* __restrict__ Vhi, __half* __restrict__ Vlo)
{
    const int b = blockIdx.z;
    const float* Vb = V + (size_t)b * LL * DD;
    __shared__ float tile[32][33];
    const int tx = threadIdx.x, ty = threadIdx.y;   // 32 x 8
    const int d0 = blockIdx.x * 32, i0 = blockIdx.y * 32;

#pragma unroll
    for (int r = 0; r < 4; r++) {
        int i = i0 + ty + r * 8;
        tile[ty + r * 8][tx] = Vb[(size_t)i * DD + d0 + tx];
    }
    __syncthreads();
    const size_t ob = (size_t)b * DD * LL;
#pragma unroll
    for (int r = 0; r < 4; r++) {
        int d = d0 + ty + r * 8;
        float v = tile[tx][ty + r * 8];
        __half h, l;
        split_half(v, h, l);
        size_t o = ob + (size_t)d * LL + i0 + tx;
        Vhi[o] = h;
        Vlo[o] = l;
    }
}

// ---------------------------------------------------------------------------
// Launch
// ---------------------------------------------------------------------------
extern "C" void kernel_launch(void* const* d_in, const int* in_sizes, int n_in,
                              void* d_out, int out_size)
{
    const float* q  = (const float*)d_in[0];
    const float* k  = (const float*)d_in[1];
    const float* v  = (const float*)d_in[2];
    const float* Wq = (const float*)d_in[3];
    const float* bq = (const float*)d_in[4];
    const float* Wk = (const float*)d_in[5];
    const float* bk = (const float*)d_in[6];
    const float* Wv = (const float*)d_in[7];
    const float* bv = (const float*)d_in[8];
    float* out = (float*)d_out;

    __half *qhi, *qlo, *khi, *klo, *pthi, *ptlo, *vthi, *vtlo;
    float *vp, *S, *c;
    cudaGetSymbolAddress((void**)&qhi,  g_qhi);
    cudaGetSymbolAddress((void**)&qlo,  g_qlo);
    cudaGetSymbolAddress((void**)&khi,  g_khi);
    cudaGetSymbolAddress((void**)&klo,  g_klo);
    cudaGetSymbolAddress((void**)&vp,   g_vp);
    cudaGetSymbolAddress((void**)&S,    g_S);
    cudaGetSymbolAddress((void**)&c,    g_c);
    cudaGetSymbolAddress((void**)&pthi, g_pthi);
    cudaGetSymbolAddress((void**)&ptlo, g_ptlo);
    cudaGetSymbolAddress((void**)&vthi, g_vthi);
    cudaGetSymbolAddress((void**)&vtlo, g_vtlo);

    // idempotent, host-side only (not a stream op): capture-safe
    cudaFuncSetAttribute(mma_nt_split,
                         cudaFuncAttributeMaxDynamicSharedMemorySize, MMA_DYN);

    // 1) Projections (Q,K -> fp16 split; V -> fp32)
    dim3 gProj(DD / TILE, (BB * LL) / TILE, 1);
    gemm_nt<<<gProj, 256>>>(q, Wq, bq, nullptr, qhi, qlo, DD, DD);
    gemm_nt<<<gProj, 256>>>(k, Wk, bk, nullptr, khi, klo, DD, DD);
    gemm_nt<<<gProj, 256>>>(v, Wv, bv, vp, nullptr, nullptr, DD, DD);

    // 2) V^T split (K-major B operand for the output GEMM)
    v_split_t<<<dim3(DD / 32, LL / 32, BB), dim3(32, 8)>>>(vp, vthi, vtlo);

    // 3) Scores: S[b,i,j] = (Q' K'^T)/16 via split-fp16 mma.sync
    mma_nt_split<<<dim3(LL / 128, LL / 128, BB), 256, MMA_DYN>>>(
        qhi, qlo, khi, klo, S,
        DD, DD, DD, LL,
        (size_t)LL * DD, (size_t)LL * DD, (size_t)LL * LL, 0.0625f);

    // 4) Per-query-row logsumexp
    rowstats<<<BB * LL, 256>>>(S, c);

    // 5) Pt = exp(S - c)^T, fp16 split
    make_pt<<<dim3(LL / 32, LL / 32, BB), dim3(32, 8)>>>(S, c, pthi, ptlo);

    // 6) out[b,j,d] = sum_i Pt[b,j,i] * Vt[b,d,i] via split-fp16 mma.sync
    mma_nt_split<<<dim3(DD / 128, LL / 128, BB), 256, MMA_DYN>>>(
        pthi, ptlo, vthi, vtlo, out,
        LL, LL, LL, DD,
        (size_t)LL * LL, (size_t)DD * LL, (size_t)LL * DD, 1.0f);
}

// round 7
// speedup vs baseline: 1.9655x; 1.1521x over previous
#include <cuda_runtime.h>
#include <cuda_fp16.h>
#include <cstdint>

#define BB   4
#define LL   4096
#define DD   256
#define TILE 128
#define KT   16
#define SPAD 132
#define NJT  (LL / 128)          // j-tiles per row = 32

// ---------------------------------------------------------------------------
// Device scratch (allocation-free)
// ---------------------------------------------------------------------------
__device__ __align__(256) __half g_qhi[BB * LL * DD];
__device__ __align__(256) __half g_qlo[BB * LL * DD];
__device__ __align__(256) __half g_khi[BB * LL * DD];
__device__ __align__(256) __half g_klo[BB * LL * DD];
__device__ __align__(256) float  g_vp [BB * LL * DD];
__device__ __align__(256) float  g_S  [(size_t)BB * LL * LL];
__device__ __align__(256) float  g_c  [BB * LL];
__device__ __align__(256) float  g_pm [(size_t)BB * LL * NJT];  // per-tile row max
__device__ __align__(256) float  g_ps [(size_t)BB * LL * NJT];  // per-tile row sumexp
__device__ __align__(256) __half g_vthi[BB * DD * LL];
__device__ __align__(256) __half g_vtlo[BB * DD * LL];

// ---------------------------------------------------------------------------
// fp32 -> fp16 two-term split
// ---------------------------------------------------------------------------
__device__ __forceinline__ void split_half(float x, __half& h, __half& l) {
    h = __float2half_rn(x);
    l = __float2half_rn(x - __half2float(h));
}

// ---------------------------------------------------------------------------
// Packed f32x2 helpers (projection GEMMs)
// ---------------------------------------------------------------------------
__device__ __forceinline__ unsigned long long ffma2(unsigned long long a,
                                                    unsigned long long b,
                                                    unsigned long long c) {
    unsigned long long d;
    asm("fma.rn.f32x2 %0, %1, %2, %3;" : "=l"(d) : "l"(a), "l"(b), "l"(c));
    return d;
}
__device__ __forceinline__ unsigned long long pack2(float x, float y) {
    unsigned long long r;
    asm("mov.b64 %0, {%1, %2};" : "=l"(r) : "f"(x), "f"(y));
    return r;
}
__device__ __forceinline__ float2 unpack2(unsigned long long p) {
    float2 r;
    asm("mov.b64 {%0, %1}, %2;" : "=f"(r.x), "=f"(r.y) : "l"(p));
    return r;
}

// ---------------------------------------------------------------------------
// Projection GEMM (FFMA2): C[M,256] = A[M,256] @ W[256,256]^T + bias.
// If OHi != null, writes fp16 split (hi/lo) instead of fp32 C.
// ---------------------------------------------------------------------------
__global__ void __launch_bounds__(256, 2)
gemm_nt(const float* __restrict__ A, const float* __restrict__ Bm,
        const float* __restrict__ bias, float* __restrict__ C,
        __half* __restrict__ OHi, __half* __restrict__ OLo,
        int K, int N)
{
    __shared__ __align__(16) float As[KT][SPAD];
    __shared__ __align__(16) float Bs[KT][SPAD];

    const int t    = threadIdx.x;
    const int m0   = blockIdx.y * TILE;
    const int n0   = blockIdx.x * TILE;
    const int warp = t >> 5, lane = t & 31;
    const int tm = (warp & 1) * 64 + (lane & 7) * 8;
    const int tn = (warp >> 1) * 32 + (lane >> 3) * 8;

    unsigned long long acc[8][4];
#pragma unroll
    for (int i = 0; i < 8; i++)
#pragma unroll
        for (int j = 0; j < 4; j++) acc[i][j] = 0ull;

    for (int k0 = 0; k0 < K; k0 += KT) {
#pragma unroll
        for (int r = 0; r < 2; r++) {
            int idx = t + 256 * r;
            int row = idx >> 2;
            int c4  = (idx & 3) * 4;
            float4 av = *(const float4*)(A  + (size_t)(m0 + row) * K + k0 + c4);
            float4 bv = *(const float4*)(Bm + (size_t)(n0 + row) * K + k0 + c4);
            As[c4 + 0][row] = av.x; As[c4 + 1][row] = av.y;
            As[c4 + 2][row] = av.z; As[c4 + 3][row] = av.w;
            Bs[c4 + 0][row] = bv.x; Bs[c4 + 1][row] = bv.y;
            Bs[c4 + 2][row] = bv.z; Bs[c4 + 3][row] = bv.w;
        }
        __syncthreads();
#pragma unroll
        for (int k = 0; k < KT; k++) {
            float4 a0 = *(const float4*)&As[k][tm];
            float4 a1 = *(const float4*)&As[k][tm + 4];
            ulonglong2 b0 = *(const ulonglong2*)&Bs[k][tn];
            ulonglong2 b1 = *(const ulonglong2*)&Bs[k][tn + 4];
            float aa[8] = {a0.x, a0.y, a0.z, a0.w, a1.x, a1.y, a1.z, a1.w};
#pragma unroll
            for (int i = 0; i < 8; i++) {
                unsigned long long ad = pack2(aa[i], aa[i]);
                acc[i][0] = ffma2(ad, b0.x, acc[i][0]);
                acc[i][1] = ffma2(ad, b0.y, acc[i][1]);
                acc[i][2] = ffma2(ad, b1.x, acc[i][2]);
                acc[i][3] = ffma2(ad, b1.y, acc[i][3]);
            }
        }
        __syncthreads();
    }

#pragma unroll
    for (int i = 0; i < 8; i++) {
        size_t rowoff = (size_t)(m0 + tm + i) * N;
#pragma unroll
        for (int jp = 0; jp < 4; jp++) {
            int col = n0 + tn + jp * 2;
            float2 vv = unpack2(acc[i][jp]);
            vv.x += bias[col];
            vv.y += bias[col + 1];
            if (OHi) {
                __half h0, l0, h1, l1;
                split_half(vv.x, h0, l0);
                split_half(vv.y, h1, l1);
                __half2 hh; hh.x = h0; hh.y = h1;
                __half2 ll; ll.x = l0; ll.y = l1;
                *(__half2*)(OHi + rowoff + col) = hh;
                *(__half2*)(OLo + rowoff + col) = ll;
            } else {
                *(float2*)(C + rowoff + col) = vv;
            }
        }
    }
}

// ---------------------------------------------------------------------------
// mma.sync m16n8k16 fp16 -> fp32
// ---------------------------------------------------------------------------
__device__ __forceinline__ void mma16816(float* d, const uint32_t* a, const uint32_t* b) {
    asm volatile(
        "mma.sync.aligned.m16n8k16.row.col.f32.f16.f16.f32 "
        "{%0,%1,%2,%3}, {%4,%5,%6,%7}, {%8,%9}, {%0,%1,%2,%3};"
        : "+f"(d[0]), "+f"(d[1]), "+f"(d[2]), "+f"(d[3])
        : "r"(a[0]), "r"(a[1]), "r"(a[2]), "r"(a[3]), "r"(b[0]), "r"(b[1]));
}

__device__ __forceinline__ uint32_t smem_u32p(const void* p) {
    uint32_t a;
    asm("{ .reg .u64 t; cvta.to.shared.u64 t, %1; cvt.u32.u64 %0, t; }"
        : "=r"(a) : "l"(p));
    return a;
}
__device__ __forceinline__ void cp_async16(uint32_t saddr, const void* g) {
    asm volatile("cp.async.cg.shared.global [%0], [%1], 16;"
                 :: "r"(saddr), "l"(g) : "memory");
}
#define CP_COMMIT()  asm volatile("cp.async.commit_group;" ::: "memory")
#define CP_WAIT1()   asm volatile("cp.async.wait_group 1;" ::: "memory")

// ---------------------------------------------------------------------------
// Score GEMM: S[128x128 tile] = scale * (Qs @ Ks^T), split-fp16 mma.sync,
// cp.async double-buffered. Epilogue additionally reduces per-row partial
// softmax stats over this tile's 128 columns -> g_pm/g_ps[(b*LL+i)*NJT + jt].
// ---------------------------------------------------------------------------
#define SROW   40
#define OPSZ   (128 * SROW * 2)     // 10240 B per operand tile
#define BUFSZ  (4 * OPSZ)           // 40960 B per buffer
#define MMA_DYN (2 * BUFSZ)         // 81920 B total

__global__ void __launch_bounds__(256)
score_mma(const __half* __restrict__ Ahg, const __half* __restrict__ Alg,
          const __half* __restrict__ Bhg, const __half* __restrict__ Blg,
          float* __restrict__ C, float* __restrict__ pm, float* __restrict__ ps,
          float scale)
{
    extern __shared__ __align__(16) char dyn[];
    const uint32_t su = smem_u32p(dyn);
    __shared__ float redm[128][4];
    __shared__ float redl[128][4];
    __shared__ float redmax[128];

    const int t = threadIdx.x;
    const int wid = t >> 5, lane = t & 31;
    const int wm = wid >> 2;
    const int wn = wid & 3;
    const int fr = lane >> 2;
    const int fc = (lane & 3) * 2;

    const size_t zqk = (size_t)LL * DD;
    Ahg += (size_t)blockIdx.z * zqk;  Alg += (size_t)blockIdx.z * zqk;
    Bhg += (size_t)blockIdx.z * zqk;  Blg += (size_t)blockIdx.z * zqk;
    C   += (size_t)blockIdx.z * LL * LL;
    const int m0 = blockIdx.y * 128;
    const int n0 = blockIdx.x * 128;

    float acc[4][4][4];
#pragma unroll
    for (int i = 0; i < 4; i++)
#pragma unroll
        for (int j = 0; j < 4; j++)
#pragma unroll
            for (int e = 0; e < 4; e++) acc[i][j][e] = 0.0f;

    const int srow = t >> 2;
    const int sq   = (t & 3) * 8;

    auto stage = [&](int b, int k0) {
        const uint32_t base = su + b * BUFSZ;
#pragma unroll
        for (int it = 0; it < 2; it++) {
            int row = srow + 64 * it;
            uint32_t so = base + row * (SROW * 2) + sq * 2;
            size_t ea = (size_t)(m0 + row) * DD + k0 + sq;
            size_t eb = (size_t)(n0 + row) * DD + k0 + sq;
            cp_async16(so + 0 * OPSZ, Ahg + ea);
            cp_async16(so + 1 * OPSZ, Alg + ea);
            cp_async16(so + 2 * OPSZ, Bhg + eb);
            cp_async16(so + 3 * OPSZ, Blg + eb);
        }
    };

    const int nchunks = DD >> 5;          // 8
    stage(0, 0);
    CP_COMMIT();

    for (int kc = 0; kc < nchunks; kc++) {
        if (kc + 1 < nchunks) stage((kc + 1) & 1, (kc + 1) << 5);
        CP_COMMIT();
        CP_WAIT1();
        __syncthreads();

        const char* p = dyn + (kc & 1) * BUFSZ;
        const __half (*sAh)[SROW] = (const __half (*)[SROW])(p + 0 * OPSZ);
        const __half (*sAl)[SROW] = (const __half (*)[SROW])(p + 1 * OPSZ);
        const __half (*sBh)[SROW] = (const __half (*)[SROW])(p + 2 * OPSZ);
        const __half (*sBl)[SROW] = (const __half (*)[SROW])(p + 3 * OPSZ);

#pragma unroll
        for (int ks = 0; ks < 32; ks += 16) {
            uint32_t ah[4][4], al[4][4], bh[4][2], bl[4][2];
#pragma unroll
            for (int mt = 0; mt < 4; mt++) {
                int r = wm * 64 + mt * 16 + fr;
                ah[mt][0] = *(const uint32_t*)&sAh[r    ][fc + ks];
                ah[mt][1] = *(const uint32_t*)&sAh[r + 8][fc + ks];
                ah[mt][2] = *(const uint32_t*)&sAh[r    ][fc + ks + 8];
                ah[mt][3] = *(const uint32_t*)&sAh[r + 8][fc + ks + 8];
                al[mt][0] = *(const uint32_t*)&sAl[r    ][fc + ks];
                al[mt][1] = *(const uint32_t*)&sAl[r + 8][fc + ks];
                al[mt][2] = *(const uint32_t*)&sAl[r    ][fc + ks + 8];
                al[mt][3] = *(const uint32_t*)&sAl[r + 8][fc + ks + 8];
            }
#pragma unroll
            for (int nt = 0; nt < 4; nt++) {
                int r = wn * 32 + nt * 8 + fr;
                bh[nt][0] = *(const uint32_t*)&sBh[r][fc + ks];
                bh[nt][1] = *(const uint32_t*)&sBh[r][fc + ks + 8];
                bl[nt][0] = *(const uint32_t*)&sBl[r][fc + ks];
                bl[nt][1] = *(const uint32_t*)&sBl[r][fc + ks + 8];
            }
#pragma unroll
            for (int mt = 0; mt < 4; mt++)
#pragma unroll
                for (int nt = 0; nt < 4; nt++) {
                    mma16816(acc[mt][nt], ah[mt], bh[nt]);
                    mma16816(acc[mt][nt], ah[mt], bl[nt]);
                    mma16816(acc[mt][nt], al[mt], bh[nt]);
                }
        }
        __syncthreads();
    }

    // ---- store S tile ----
#pragma unroll
    for (int mt = 0; mt < 4; mt++) {
        int row = m0 + wm * 64 + mt * 16 + fr;
#pragma unroll
        for (int nt = 0; nt < 4; nt++) {
            int col = n0 + wn * 32 + nt * 8 + fc;
            float2 v0, v1;
            v0.x = acc[mt][nt][0] * scale;
            v0.y = acc[mt][nt][1] * scale;
            v1.x = acc[mt][nt][2] * scale;
            v1.y = acc[mt][nt][3] * scale;
            *(float2*)(C + (size_t)row * LL + col)       = v0;
            *(float2*)(C + (size_t)(row + 8) * LL + col) = v1;
        }
    }

    // ---- per-row partial softmax stats over this tile's 128 columns ----
    // pass A: per-row max (per thread over its 8 cols, then q-lane shuffle)
    float rm[4][2];
#pragma unroll
    for (int mt = 0; mt < 4; mt++)
#pragma unroll
        for (int h = 0; h < 2; h++) {
            float m = -3.0e38f;
#pragma unroll
            for (int nt = 0; nt < 4; nt++) {
                m = fmaxf(m, acc[mt][nt][2 * h]     * scale);
                m = fmaxf(m, acc[mt][nt][2 * h + 1] * scale);
            }
#pragma unroll
            for (int o = 1; o <= 2; o <<= 1)
                m = fmaxf(m, __shfl_xor_sync(0xffffffffu, m, o));
            rm[mt][h] = m;
        }
    if ((lane & 3) == 0) {
#pragma unroll
        for (int mt = 0; mt < 4; mt++)
#pragma unroll
            for (int h = 0; h < 2; h++)
                redm[wm * 64 + mt * 16 + fr + 8 * h][wn] = rm[mt][h];
    }
    __syncthreads();
    if (t < 128)
        redmax[t] = fmaxf(fmaxf(redm[t][0], redm[t][1]),
                          fmaxf(redm[t][2], redm[t][3]));
    __syncthreads();
    // pass B: per-row sumexp relative to tile-row max
#pragma unroll
    for (int mt = 0; mt < 4; mt++)
#pragma unroll
        for (int h = 0; h < 2; h++) {
            int r = wm * 64 + mt * 16 + fr + 8 * h;
            float rmx = redmax[r];
            float s = 0.0f;
#pragma unroll
            for (int nt = 0; nt < 4; nt++) {
                s += __expf(acc[mt][nt][2 * h]     * scale - rmx);
                s += __expf(acc[mt][nt][2 * h + 1] * scale - rmx);
            }
#pragma unroll
            for (int o = 1; o <= 2; o <<= 1)
                s += __shfl_xor_sync(0xffffffffu, s, o);
            if ((lane & 3) == 0) redl[r][wn] = s;
        }
    __syncthreads();
    if (t < 128) {
        float sum = redl[t][0] + redl[t][1] + redl[t][2] + redl[t][3];
        size_t o = ((size_t)blockIdx.z * LL + m0 + t) * NJT + blockIdx.x;
        pm[o] = redmax[t];
        ps[o] = sum;
    }
}

// ---------------------------------------------------------------------------
// Combine partials: c[row] = M + log( sum_jt ps*exp(pm - M) ), M = max pm
// ---------------------------------------------------------------------------
__global__ void __launch_bounds__(256)
combine(const float* __restrict__ pm, const float* __restrict__ ps,
        float* __restrict__ c)
{
    const int row = blockIdx.x * 8 + threadIdx.y;
    const int tx  = threadIdx.x;
    size_t base = (size_t)row * NJT + tx;
    float m = pm[base];
    float l = ps[base];
    float M = m;
#pragma unroll
    for (int o = 16; o > 0; o >>= 1)
        M = fmaxf(M, __shfl_xor_sync(0xffffffffu, M, o));
    float s = l * __expf(m - M);
#pragma unroll
    for (int o = 16; o > 0; o >>= 1)
        s += __shfl_xor_sync(0xffffffffu, s, o);
    if (tx == 0) c[row] = M + __logf(s);
}

// ---------------------------------------------------------------------------
// Fused output GEMM: out[b,j,d] = sum_i exp(S[b,i,j]-c[b,i]) * V'[b,i,d]
// A operand built on the fly: stage S (fp32, coalesced rows) via cp.async,
// exp + fp16-split + transpose into smem [j][i] tiles. B operand = Vt hi/lo
// (cp.async double-buffered). Same 3-term split-fp16 mma.sync core.
// ---------------------------------------------------------------------------
#define AOS_SSZ  (32 * 132 * 4)            // 16896 B per S staging buffer
#define AOS_AH   (2 * AOS_SSZ)             // 33792
#define AOS_AL   (AOS_AH + OPSZ)           // 44032
#define AOS_B0   (AOS_AL + OPSZ)           // 54272, 2 buffers of 2*OPSZ
#define AOS_DYN  (AOS_B0 + 2 * 2 * OPSZ)   // 95232 B

__global__ void __launch_bounds__(256)
attn_out_fused(const float* __restrict__ S, const float* __restrict__ cst,
               const __half* __restrict__ Vth, const __half* __restrict__ Vtl,
               float* __restrict__ out)
{
    extern __shared__ __align__(16) char dyn[];
    __shared__ float sc[32];
    const uint32_t su = smem_u32p(dyn);

    const int t = threadIdx.x;
    const int wid = t >> 5, lane = t & 31;
    const int wm = wid >> 2;          // j-axis warp
    const int wn = wid & 3;           // d-axis warp
    const int fr = lane >> 2;
    const int fc = (lane & 3) * 2;

    const int b = blockIdx.z;
    const float* Sb  = S   + (size_t)b * LL * LL;
    const float* cb  = cst + (size_t)b * LL;
    const __half* Vh = Vth + (size_t)b * DD * LL;
    const __half* Vl = Vtl + (size_t)b * DD * LL;
    float* Ob = out + (size_t)b * LL * DD;

    const int j0 = blockIdx.y * 128;
    const int d0 = blockIdx.x * 128;

    float acc[4][4][4];
#pragma unroll
    for (int i = 0; i < 4; i++)
#pragma unroll
        for (int j = 0; j < 4; j++)
#pragma unroll
            for (int e = 0; e < 4; e++) acc[i][j][e] = 0.0f;

    const int srow = t >> 2;
    const int sq   = (t & 3) * 8;

    auto stageB = [&](int buf, int i0) {
        const uint32_t base = su + AOS_B0 + buf * (2 * OPSZ);
#pragma unroll
        for (int it = 0; it < 2; it++) {
            int row = srow + 64 * it;
            uint32_t so = base + row * (SROW * 2) + sq * 2;
            size_t e = (size_t)(d0 + row) * LL + i0 + sq;
            cp_async16(so,        Vh + e);
            cp_async16(so + OPSZ, Vl + e);
        }
    };
    auto stageS = [&](int buf, int i0) {
        const uint32_t base = su + buf * AOS_SSZ;
#pragma unroll
        for (int u = 0; u < 4; u++) {
            int idx = t + 256 * u;
            int row = idx >> 5;
            int c4  = (idx & 31) * 4;
            cp_async16(base + row * 528 + c4 * 4,
                       Sb + (size_t)(i0 + row) * LL + j0 + c4);
        }
    };

    const int nchunks = LL >> 5;       // 128
    stageB(0, 0);
    stageS(0, 0);
    CP_COMMIT();

    const int jl = t & 127;            // transform: this thread's j column
    const int ih = (t >> 7) * 16;      // and i half (0 or 16)

    for (int kc = 0; kc < nchunks; kc++) {
        const int i0 = kc << 5;
        if (kc + 1 < nchunks) {
            stageB((kc + 1) & 1, i0 + 32);
            stageS((kc + 1) & 1, i0 + 32);
        }
        CP_COMMIT();
        CP_WAIT1();
        if (t < 32) sc[t] = cb[i0 + t];
        __syncthreads();

        // ---- transform: exp + split + transpose into sAh/sAl [j][i] ----
        {
            const float* sSp = (const float*)(dyn + (kc & 1) * AOS_SSZ);
            __half2 hb[8], lb[8];
#pragma unroll
            for (int ii = 0; ii < 16; ii += 2) {
                float s0 = sSp[(ih + ii)     * 132 + jl];
                float s1 = sSp[(ih + ii + 1) * 132 + jl];
                float p0 = __expf(s0 - sc[ih + ii]);
                float p1 = __expf(s1 - sc[ih + ii + 1]);
                __half h0 = __float2half_rn(p0);
                __half h1 = __float2half_rn(p1);
                __half l0 = __float2half_rn(p0 - __half2float(h0));
                __half l1 = __float2half_rn(p1 - __half2float(h1));
                hb[ii >> 1] = __halves2half2(h0, h1);
                lb[ii >> 1] = __halves2half2(l0, l1);
            }
            char* ah = dyn + AOS_AH + jl * (SROW * 2) + ih * 2;
            char* al = dyn + AOS_AL + jl * (SROW * 2) + ih * 2;
            *(uint4*)(ah)      = *(uint4*)&hb[0];
            *(uint4*)(ah + 16) = *(uint4*)&hb[4];
            *(uint4*)(al)      = *(uint4*)&lb[0];
            *(uint4*)(al + 16) = *(uint4*)&lb[4];
        }
        __syncthreads();

        // ---- MMA over the 32-i chunk ----
        const __half (*sAh)[SROW] = (const __half (*)[SROW])(dyn + AOS_AH);
        const __half (*sAl)[SROW] = (const __half (*)[SROW])(dyn + AOS_AL);
        const char* pb = dyn + AOS_B0 + (kc & 1) * (2 * OPSZ);
        const __half (*sBh)[SROW] = (const __half (*)[SROW])(pb);
        const __half (*sBl)[SROW] = (const __half (*)[SROW])(pb + OPSZ);

#pragma unroll
        for (int ks = 0; ks < 32; ks += 16) {
            uint32_t ah[4][4], al[4][4], bh[4][2], bl[4][2];
#pragma unroll
            for (int mt = 0; mt < 4; mt++) {
                int r = wm * 64 + mt * 16 + fr;
                ah[mt][0] = *(const uint32_t*)&sAh[r    ][fc + ks];
                ah[mt][1] = *(const uint32_t*)&sAh[r + 8][fc + ks];
                ah[mt][2] = *(const uint32_t*)&sAh[r    ][fc + ks + 8];
                ah[mt][3] = *(const uint32_t*)&sAh[r + 8][fc + ks + 8];
                al[mt][0] = *(const uint32_t*)&sAl[r    ][fc + ks];
                al[mt][1] = *(const uint32_t*)&sAl[r + 8][fc + ks];
                al[mt][2] = *(const uint32_t*)&sAl[r    ][fc + ks + 8];
                al[mt][3] = *(const uint32_t*)&sAl[r + 8][fc + ks + 8];
            }
#pragma unroll
            for (int nt = 0; nt < 4; nt++) {
                int r = wn * 32 + nt * 8 + fr;
                bh[nt][0] = *(const uint32_t*)&sBh[r][fc + ks];
                bh[nt][1] = *(const uint32_t*)&sBh[r][fc + ks + 8];
                bl[nt][0] = *(const uint32_t*)&sBl[r][fc + ks];
                bl[nt][1] = *(const uint32_t*)&sBl[r][fc + ks + 8];
            }
#pragma unroll
            for (int mt = 0; mt < 4; mt++)
#pragma unroll
                for (int nt = 0; nt < 4; nt++) {
                    mma16816(acc[mt][nt], ah[mt], bh[nt]);
                    mma16816(acc[mt][nt], ah[mt], bl[nt]);
                    mma16816(acc[mt][nt], al[mt], bh[nt]);
                }
        }
        __syncthreads();
    }

    // ---- epilogue: out[j][d] ----
#pragma unroll
    for (int mt = 0; mt < 4; mt++) {
        int row = j0 + wm * 64 + mt * 16 + fr;
#pragma unroll
        for (int nt = 0; nt < 4; nt++) {
            int col = d0 + wn * 32 + nt * 8 + fc;
            float2 v0, v1;
            v0.x = acc[mt][nt][0];
            v0.y = acc[mt][nt][1];
            v1.x = acc[mt][nt][2];
            v1.y = acc[mt][nt][3];
            *(float2*)(Ob + (size_t)row * DD + col)       = v0;
            *(float2*)(Ob + (size_t)(row + 8) * DD + col) = v1;
        }
    }
}

// ---------------------------------------------------------------------------
// V^T build: Vt[b][d][i] = split(Vp[b][i][d])
// ---------------------------------------------------------------------------
__global__ void __launch_bounds__(256)
v_split_t(const float* __restrict__ V,
          __half* __restrict__ Vhi, __half* __restrict__ Vlo)
{
    const int b = blockIdx.z;
    const float* Vb = V + (size_t)b * LL * DD;
    __shared__ float tile[32][33];
    const int tx = threadIdx.x, ty = threadIdx.y;   // 32 x 8
    const int d0 = blockIdx.x * 32, i0 = blockIdx.y * 32;

#pragma unroll
    for (int r = 0; r < 4; r++) {
        int i = i0 + ty + r * 8;
        tile[ty + r * 8][tx] = Vb[(size_t)i * DD + d0 + tx];
    }
    __syncthreads();
    const size_t ob = (size_t)b * DD * LL;
#pragma unroll
    for (int r = 0; r < 4; r++) {
        int d = d0 + ty + r * 8;
        float v = tile[tx][ty + r * 8];
        __half h, l;
        split_half(v, h, l);
        size_t o = ob + (size_t)d * LL + i0 + tx;
        Vhi[o] = h;
        Vlo[o] = l;
    }
}

// ---------------------------------------------------------------------------
// Launch
// ---------------------------------------------------------------------------
extern "C" void kernel_launch(void* const* d_in, const int* in_sizes, int n_in,
                              void* d_out, int out_size)
{
    const float* q  = (const float*)d_in[0];
    const float* k  = (const float*)d_in[1];
    const float* v  = (const float*)d_in[2];
    const float* Wq = (const float*)d_in[3];
    const float* bq = (const float*)d_in[4];
    const float* Wk = (const float*)d_in[5];
    const float* bk = (const float*)d_in[6];
    const float* Wv = (const float*)d_in[7];
    const float* bv = (const float*)d_in[8];
    float* out = (float*)d_out;

    __half *qhi, *qlo, *khi, *klo, *vthi, *vtlo;
    float *vp, *S, *c, *pm, *ps;
    cudaGetSymbolAddress((void**)&qhi,  g_qhi);
    cudaGetSymbolAddress((void**)&qlo,  g_qlo);
    cudaGetSymbolAddress((void**)&khi,  g_khi);
    cudaGetSymbolAddress((void**)&klo,  g_klo);
    cudaGetSymbolAddress((void**)&vp,   g_vp);
    cudaGetSymbolAddress((void**)&S,    g_S);
    cudaGetSymbolAddress((void**)&c,    g_c);
    cudaGetSymbolAddress((void**)&pm,   g_pm);
    cudaGetSymbolAddress((void**)&ps,   g_ps);
    cudaGetSymbolAddress((void**)&vthi, g_vthi);
    cudaGetSymbolAddress((void**)&vtlo, g_vtlo);

    // host-side attribute setters: idempotent, capture-safe
    cudaFuncSetAttribute(score_mma,
                         cudaFuncAttributeMaxDynamicSharedMemorySize, MMA_DYN);
    cudaFuncSetAttribute(attn_out_fused,
                         cudaFuncAttributeMaxDynamicSharedMemorySize, AOS_DYN);

    // 1) Projections (Q,K -> fp16 split; V -> fp32)
    dim3 gProj(DD / TILE, (BB * LL) / TILE, 1);
    gemm_nt<<<gProj, 256>>>(q, Wq, bq, nullptr, qhi, qlo, DD, DD);
    gemm_nt<<<gProj, 256>>>(k, Wk, bk, nullptr, khi, klo, DD, DD);
    gemm_nt<<<gProj, 256>>>(v, Wv, bv, vp, nullptr, nullptr, DD, DD);

    // 2) V^T split (K-major B operand for the output GEMM)
    v_split_t<<<dim3(DD / 32, LL / 32, BB), dim3(32, 8)>>>(vp, vthi, vtlo);

    // 3) Scores + per-tile softmax partials
    score_mma<<<dim3(LL / 128, LL / 128, BB), 256, MMA_DYN>>>(
        qhi, qlo, khi, klo, S, pm, ps, 0.0625f);

    // 4) Combine partials -> c
    combine<<<(BB * LL) / 8, dim3(32, 8)>>>(pm, ps, c);

    // 5) Fused: out[b,j,d] = sum_i exp(S-c) * V'
    attn_out_fused<<<dim3(DD / 128, LL / 128, BB), 256, AOS_DYN>>>(
        S, c, vthi, vtlo, out);
}

// round 8
// speedup vs baseline: 2.1112x; 1.0741x over previous
#include <cuda_runtime.h>
#include <cuda_fp16.h>
#include <cstdint>

#define BB   4
#define LL   4096
#define DD   256
#define TILE 128
#define KT   16
#define SPAD 132
#define NJT  (LL / 128)          // j-tiles per row = 32

// ---------------------------------------------------------------------------
// Device scratch (allocation-free)
// ---------------------------------------------------------------------------
__device__ __align__(256) __half g_qhi[BB * LL * DD];
__device__ __align__(256) __half g_qlo[BB * LL * DD];
__device__ __align__(256) __half g_khi[BB * LL * DD];
__device__ __align__(256) __half g_klo[BB * LL * DD];
__device__ __align__(256) float  g_vp [BB * LL * DD];
__device__ __align__(256) float  g_S  [(size_t)BB * LL * LL];
__device__ __align__(256) float  g_c  [BB * LL];
__device__ __align__(256) float  g_pm [(size_t)BB * LL * NJT];
__device__ __align__(256) float  g_ps [(size_t)BB * LL * NJT];
__device__ __align__(256) __half g_vthi[BB * DD * LL];
__device__ __align__(256) __half g_vtlo[BB * DD * LL];

// ---------------------------------------------------------------------------
// fp32 -> fp16 two-term split
// ---------------------------------------------------------------------------
__device__ __forceinline__ void split_half(float x, __half& h, __half& l) {
    h = __float2half_rn(x);
    l = __float2half_rn(x - __half2float(h));
}

// ---------------------------------------------------------------------------
// Packed f32x2 helpers (projection GEMMs)
// ---------------------------------------------------------------------------
__device__ __forceinline__ unsigned long long ffma2(unsigned long long a,
                                                    unsigned long long b,
                                                    unsigned long long c) {
    unsigned long long d;
    asm("fma.rn.f32x2 %0, %1, %2, %3;" : "=l"(d) : "l"(a), "l"(b), "l"(c));
    return d;
}
__device__ __forceinline__ unsigned long long pack2(float x, float y) {
    unsigned long long r;
    asm("mov.b64 %0, {%1, %2};" : "=l"(r) : "f"(x), "f"(y));
    return r;
}
__device__ __forceinline__ float2 unpack2(unsigned long long p) {
    float2 r;
    asm("mov.b64 {%0, %1}, %2;" : "=f"(r.x), "=f"(r.y) : "l"(p));
    return r;
}

// ---------------------------------------------------------------------------
// Projection GEMM (FFMA2): C[M,256] = A[M,256] @ W[256,256]^T + bias.
// ---------------------------------------------------------------------------
__global__ void __launch_bounds__(256, 2)
gemm_nt(const float* __restrict__ A, const float* __restrict__ Bm,
        const float* __restrict__ bias, float* __restrict__ C,
        __half* __restrict__ OHi, __half* __restrict__ OLo,
        int K, int N)
{
    __shared__ __align__(16) float As[KT][SPAD];
    __shared__ __align__(16) float Bs[KT][SPAD];

    const int t    = threadIdx.x;
    const int m0   = blockIdx.y * TILE;
    const int n0   = blockIdx.x * TILE;
    const int warp = t >> 5, lane = t & 31;
    const int tm = (warp & 1) * 64 + (lane & 7) * 8;
    const int tn = (warp >> 1) * 32 + (lane >> 3) * 8;

    unsigned long long acc[8][4];
#pragma unroll
    for (int i = 0; i < 8; i++)
#pragma unroll
        for (int j = 0; j < 4; j++) acc[i][j] = 0ull;

    for (int k0 = 0; k0 < K; k0 += KT) {
#pragma unroll
        for (int r = 0; r < 2; r++) {
            int idx = t + 256 * r;
            int row = idx >> 2;
            int c4  = (idx & 3) * 4;
            float4 av = *(const float4*)(A  + (size_t)(m0 + row) * K + k0 + c4);
            float4 bv = *(const float4*)(Bm + (size_t)(n0 + row) * K + k0 + c4);
            As[c4 + 0][row] = av.x; As[c4 + 1][row] = av.y;
            As[c4 + 2][row] = av.z; As[c4 + 3][row] = av.w;
            Bs[c4 + 0][row] = bv.x; Bs[c4 + 1][row] = bv.y;
            Bs[c4 + 2][row] = bv.z; Bs[c4 + 3][row] = bv.w;
        }
        __syncthreads();
#pragma unroll
        for (int k = 0; k < KT; k++) {
            float4 a0 = *(const float4*)&As[k][tm];
            float4 a1 = *(const float4*)&As[k][tm + 4];
            ulonglong2 b0 = *(const ulonglong2*)&Bs[k][tn];
            ulonglong2 b1 = *(const ulonglong2*)&Bs[k][tn + 4];
            float aa[8] = {a0.x, a0.y, a0.z, a0.w, a1.x, a1.y, a1.z, a1.w};
#pragma unroll
            for (int i = 0; i < 8; i++) {
                unsigned long long ad = pack2(aa[i], aa[i]);
                acc[i][0] = ffma2(ad, b0.x, acc[i][0]);
                acc[i][1] = ffma2(ad, b0.y, acc[i][1]);
                acc[i][2] = ffma2(ad, b1.x, acc[i][2]);
                acc[i][3] = ffma2(ad, b1.y, acc[i][3]);
            }
        }
        __syncthreads();
    }

#pragma unroll
    for (int i = 0; i < 8; i++) {
        size_t rowoff = (size_t)(m0 + tm + i) * N;
#pragma unroll
        for (int jp = 0; jp < 4; jp++) {
            int col = n0 + tn + jp * 2;
            float2 vv = unpack2(acc[i][jp]);
            vv.x += bias[col];
            vv.y += bias[col + 1];
            if (OHi) {
                __half h0, l0, h1, l1;
                split_half(vv.x, h0, l0);
                split_half(vv.y, h1, l1);
                __half2 hh; hh.x = h0; hh.y = h1;
                __half2 ll; ll.x = l0; ll.y = l1;
                *(__half2*)(OHi + rowoff + col) = hh;
                *(__half2*)(OLo + rowoff + col) = ll;
            } else {
                *(float2*)(C + rowoff + col) = vv;
            }
        }
    }
}

// ---------------------------------------------------------------------------
// mma.sync m16n8k16 fp16 -> fp32 ; ldmatrix fragment loads
// ---------------------------------------------------------------------------
__device__ __forceinline__ void mma16816(float* d, const uint32_t* a, const uint32_t* b) {
    asm volatile(
        "mma.sync.aligned.m16n8k16.row.col.f32.f16.f16.f32 "
        "{%0,%1,%2,%3}, {%4,%5,%6,%7}, {%8,%9}, {%0,%1,%2,%3};"
        : "+f"(d[0]), "+f"(d[1]), "+f"(d[2]), "+f"(d[3])
        : "r"(a[0]), "r"(a[1]), "r"(a[2]), "r"(a[3]), "r"(b[0]), "r"(b[1]));
}
__device__ __forceinline__ void ldm_x4(uint32_t* r, uint32_t saddr) {
    asm volatile("ldmatrix.sync.aligned.m8n8.x4.shared.b16 {%0,%1,%2,%3}, [%4];"
                 : "=r"(r[0]), "=r"(r[1]), "=r"(r[2]), "=r"(r[3]) : "r"(saddr));
}

__device__ __forceinline__ uint32_t smem_u32p(const void* p) {
    uint32_t a;
    asm("{ .reg .u64 t; cvta.to.shared.u64 t, %1; cvt.u32.u64 %0, t; }"
        : "=r"(a) : "l"(p));
    return a;
}
__device__ __forceinline__ void cp_async16(uint32_t saddr, const void* g) {
    asm volatile("cp.async.cg.shared.global [%0], [%1], 16;"
                 :: "r"(saddr), "l"(g) : "memory");
}
#define CP_COMMIT()  asm volatile("cp.async.commit_group;" ::: "memory")
#define CP_WAIT1()   asm volatile("cp.async.wait_group 1;" ::: "memory")

#define SROW   40
#define PITCH  (SROW * 2)           // 80 B row pitch
#define OPSZ   (128 * PITCH)        // 10240 B per operand tile
#define BUFSZ  (4 * OPSZ)           // 40960 B per buffer
#define MMA_DYN (2 * BUFSZ)         // 81920 B

// Shared inner compute: one k16 step with ldmatrix loads + 48 MMAs.
// aoffh/aoffl/boffh/boffl are u32 smem addresses of tile bases.
#define K16_STEP(ks, aoffh, aoffl, boffh, boffl)                               \
    do {                                                                       \
        uint32_t ah[4][4], al[4][4], bh[4][2], bl[4][2];                       \
        _Pragma("unroll")                                                      \
        for (int mt = 0; mt < 4; mt++) {                                       \
            uint32_t ra = (uint32_t)(wm * 64 + mt * 16 + lar) * PITCH          \
                        + ((ks) + lac) * 2;                                    \
            ldm_x4(ah[mt], (aoffh) + ra);                                      \
            ldm_x4(al[mt], (aoffl) + ra);                                      \
        }                                                                      \
        _Pragma("unroll")                                                      \
        for (int pp = 0; pp < 2; pp++) {                                       \
            uint32_t rb = (uint32_t)(wn * 32 + pp * 16 + lbr) * PITCH          \
                        + ((ks) + lbc) * 2;                                    \
            uint32_t tb[4];                                                    \
            ldm_x4(tb, (boffh) + rb);                                          \
            bh[2 * pp][0] = tb[0]; bh[2 * pp][1] = tb[1];                      \
            bh[2 * pp + 1][0] = tb[2]; bh[2 * pp + 1][1] = tb[3];              \
            ldm_x4(tb, (boffl) + rb);                                          \
            bl[2 * pp][0] = tb[0]; bl[2 * pp][1] = tb[1];                      \
            bl[2 * pp + 1][0] = tb[2]; bl[2 * pp + 1][1] = tb[3];              \
        }                                                                      \
        _Pragma("unroll")                                                      \
        for (int mt = 0; mt < 4; mt++)                                         \
            _Pragma("unroll")                                                  \
            for (int nt = 0; nt < 4; nt++) {                                   \
                mma16816(acc[mt][nt], ah[mt], bh[nt]);                         \
                mma16816(acc[mt][nt], ah[mt], bl[nt]);                         \
                mma16816(acc[mt][nt], al[mt], bh[nt]);                         \
            }                                                                  \
    } while (0)

// ---------------------------------------------------------------------------
// Score GEMM + per-tile softmax partials
// ---------------------------------------------------------------------------
__global__ void __launch_bounds__(256)
score_mma(const __half* __restrict__ Ahg, const __half* __restrict__ Alg,
          const __half* __restrict__ Bhg, const __half* __restrict__ Blg,
          float* __restrict__ C, float* __restrict__ pm, float* __restrict__ ps,
          float scale)
{
    extern __shared__ __align__(16) char dyn[];
    const uint32_t su = smem_u32p(dyn);
    __shared__ float redm[128][4];
    __shared__ float redl[128][4];
    __shared__ float redmax[128];

    const int t = threadIdx.x;
    const int wid = t >> 5, lane = t & 31;
    const int wm = wid >> 2;
    const int wn = wid & 3;
    const int fr = lane >> 2;
    const int fc = (lane & 3) * 2;
    // ldmatrix per-lane sub-offsets
    const int lar = (lane & 7) + ((lane >> 3) & 1) * 8;  // A row within 16
    const int lac = (lane >> 4) * 8;                     // A col within 16
    const int lbr = (lane & 7) + (lane >> 4) * 8;        // B row within 16
    const int lbc = ((lane >> 3) & 1) * 8;               // B col within 16

    const size_t zqk = (size_t)LL * DD;
    Ahg += (size_t)blockIdx.z * zqk;  Alg += (size_t)blockIdx.z * zqk;
    Bhg += (size_t)blockIdx.z * zqk;  Blg += (size_t)blockIdx.z * zqk;
    C   += (size_t)blockIdx.z * LL * LL;
    const int m0 = blockIdx.y * 128;
    const int n0 = blockIdx.x * 128;

    float acc[4][4][4];
#pragma unroll
    for (int i = 0; i < 4; i++)
#pragma unroll
        for (int j = 0; j < 4; j++)
#pragma unroll
            for (int e = 0; e < 4; e++) acc[i][j][e] = 0.0f;

    const int srow = t >> 2;
    const int sq   = (t & 3) * 8;

    auto stage = [&](int b, int k0) {
        const uint32_t base = su + b * BUFSZ;
#pragma unroll
        for (int it = 0; it < 2; it++) {
            int row = srow + 64 * it;
            uint32_t so = base + row * PITCH + sq * 2;
            size_t ea = (size_t)(m0 + row) * DD + k0 + sq;
            size_t eb = (size_t)(n0 + row) * DD + k0 + sq;
            cp_async16(so + 0 * OPSZ, Ahg + ea);
            cp_async16(so + 1 * OPSZ, Alg + ea);
            cp_async16(so + 2 * OPSZ, Bhg + eb);
            cp_async16(so + 3 * OPSZ, Blg + eb);
        }
    };

    const int nchunks = DD >> 5;          // 8
    stage(0, 0);
    CP_COMMIT();

    for (int kc = 0; kc < nchunks; kc++) {
        if (kc + 1 < nchunks) stage((kc + 1) & 1, (kc + 1) << 5);
        CP_COMMIT();
        CP_WAIT1();
        __syncthreads();

        const uint32_t bb = su + (kc & 1) * BUFSZ;
        K16_STEP(0,  bb, bb + OPSZ, bb + 2 * OPSZ, bb + 3 * OPSZ);
        K16_STEP(16, bb, bb + OPSZ, bb + 2 * OPSZ, bb + 3 * OPSZ);
        __syncthreads();
    }

    // ---- store S tile ----
#pragma unroll
    for (int mt = 0; mt < 4; mt++) {
        int row = m0 + wm * 64 + mt * 16 + fr;
#pragma unroll
        for (int nt = 0; nt < 4; nt++) {
            int col = n0 + wn * 32 + nt * 8 + fc;
            float2 v0, v1;
            v0.x = acc[mt][nt][0] * scale;
            v0.y = acc[mt][nt][1] * scale;
            v1.x = acc[mt][nt][2] * scale;
            v1.y = acc[mt][nt][3] * scale;
            *(float2*)(C + (size_t)row * LL + col)       = v0;
            *(float2*)(C + (size_t)(row + 8) * LL + col) = v1;
        }
    }

    // ---- per-row partial softmax stats ----
    float rm[4][2];
#pragma unroll
    for (int mt = 0; mt < 4; mt++)
#pragma unroll
        for (int h = 0; h < 2; h++) {
            float m = -3.0e38f;
#pragma unroll
            for (int nt = 0; nt < 4; nt++) {
                m = fmaxf(m, acc[mt][nt][2 * h]     * scale);
                m = fmaxf(m, acc[mt][nt][2 * h + 1] * scale);
            }
#pragma unroll
            for (int o = 1; o <= 2; o <<= 1)
                m = fmaxf(m, __shfl_xor_sync(0xffffffffu, m, o));
            rm[mt][h] = m;
        }
    if ((lane & 3) == 0) {
#pragma unroll
        for (int mt = 0; mt < 4; mt++)
#pragma unroll
            for (int h = 0; h < 2; h++)
                redm[wm * 64 + mt * 16 + fr + 8 * h][wn] = rm[mt][h];
    }
    __syncthreads();
    if (t < 128)
        redmax[t] = fmaxf(fmaxf(redm[t][0], redm[t][1]),
                          fmaxf(redm[t][2], redm[t][3]));
    __syncthreads();
#pragma unroll
    for (int mt = 0; mt < 4; mt++)
#pragma unroll
        for (int h = 0; h < 2; h++) {
            int r = wm * 64 + mt * 16 + fr + 8 * h;
            float rmx = redmax[r];
            float s = 0.0f;
#pragma unroll
            for (int nt = 0; nt < 4; nt++) {
                s += __expf(acc[mt][nt][2 * h]     * scale - rmx);
                s += __expf(acc[mt][nt][2 * h + 1] * scale - rmx);
            }
#pragma unroll
            for (int o = 1; o <= 2; o <<= 1)
                s += __shfl_xor_sync(0xffffffffu, s, o);
            if ((lane & 3) == 0) redl[r][wn] = s;
        }
    __syncthreads();
    if (t < 128) {
        float sum = redl[t][0] + redl[t][1] + redl[t][2] + redl[t][3];
        size_t o = ((size_t)blockIdx.z * LL + m0 + t) * NJT + blockIdx.x;
        pm[o] = redmax[t];
        ps[o] = sum;
    }
}

// ---------------------------------------------------------------------------
// Combine partials: c[row] = M + log( sum_jt ps*exp(pm - M) )
// ---------------------------------------------------------------------------
__global__ void __launch_bounds__(256)
combine(const float* __restrict__ pm, const float* __restrict__ ps,
        float* __restrict__ c)
{
    const int row = blockIdx.x * 8 + threadIdx.y;
    const int tx  = threadIdx.x;
    size_t base = (size_t)row * NJT + tx;
    float m = pm[base];
    float l = ps[base];
    float M = m;
#pragma unroll
    for (int o = 16; o > 0; o >>= 1)
        M = fmaxf(M, __shfl_xor_sync(0xffffffffu, M, o));
    float s = l * __expf(m - M);
#pragma unroll
    for (int o = 16; o > 0; o >>= 1)
        s += __shfl_xor_sync(0xffffffffu, s, o);
    if (tx == 0) c[row] = M + __logf(s);
}

// ---------------------------------------------------------------------------
// Fused output GEMM: out[b,j,d] = sum_i exp(S[b,i,j]-c[b,i]) * V'[b,i,d]
// ---------------------------------------------------------------------------
#define AOS_SSZ  (32 * 132 * 4)
#define AOS_AH   (2 * AOS_SSZ)
#define AOS_AL   (AOS_AH + OPSZ)
#define AOS_B0   (AOS_AL + OPSZ)
#define AOS_DYN  (AOS_B0 + 2 * 2 * OPSZ)

__global__ void __launch_bounds__(256)
attn_out_fused(const float* __restrict__ S, const float* __restrict__ cst,
               const __half* __restrict__ Vth, const __half* __restrict__ Vtl,
               float* __restrict__ out)
{
    extern __shared__ __align__(16) char dyn[];
    __shared__ float sc[32];
    const uint32_t su = smem_u32p(dyn);

    const int t = threadIdx.x;
    const int wid = t >> 5, lane = t & 31;
    const int wm = wid >> 2;
    const int wn = wid & 3;
    const int fr = lane >> 2;
    const int fc = (lane & 3) * 2;
    const int lar = (lane & 7) + ((lane >> 3) & 1) * 8;
    const int lac = (lane >> 4) * 8;
    const int lbr = (lane & 7) + (lane >> 4) * 8;
    const int lbc = ((lane >> 3) & 1) * 8;

    const int b = blockIdx.z;
    const float* Sb  = S   + (size_t)b * LL * LL;
    const float* cb  = cst + (size_t)b * LL;
    const __half* Vh = Vth + (size_t)b * DD * LL;
    const __half* Vl = Vtl + (size_t)b * DD * LL;
    float* Ob = out + (size_t)b * LL * DD;

    const int j0 = blockIdx.y * 128;
    const int d0 = blockIdx.x * 128;

    float acc[4][4][4];
#pragma unroll
    for (int i = 0; i < 4; i++)
#pragma unroll
        for (int j = 0; j < 4; j++)
#pragma unroll
            for (int e = 0; e < 4; e++) acc[i][j][e] = 0.0f;

    const int srow = t >> 2;
    const int sq   = (t & 3) * 8;

    auto stageB = [&](int buf, int i0) {
        const uint32_t base = su + AOS_B0 + buf * (2 * OPSZ);
#pragma unroll
        for (int it = 0; it < 2; it++) {
            int row = srow + 64 * it;
            uint32_t so = base + row * PITCH + sq * 2;
            size_t e = (size_t)(d0 + row) * LL + i0 + sq;
            cp_async16(so,        Vh + e);
            cp_async16(so + OPSZ, Vl + e);
        }
    };
    auto stageS = [&](int buf, int i0) {
        const uint32_t base = su + buf * AOS_SSZ;
#pragma unroll
        for (int u = 0; u < 4; u++) {
            int idx = t + 256 * u;
            int row = idx >> 5;
            int c4  = (idx & 31) * 4;
            cp_async16(base + row * 528 + c4 * 4,
                       Sb + (size_t)(i0 + row) * LL + j0 + c4);
        }
    };

    const int nchunks = LL >> 5;       // 128
    stageB(0, 0);
    stageS(0, 0);
    CP_COMMIT();

    const int jl = t & 127;
    const int ih = (t >> 7) * 16;

    for (int kc = 0; kc < nchunks; kc++) {
        const int i0 = kc << 5;
        if (kc + 1 < nchunks) {
            stageB((kc + 1) & 1, i0 + 32);
            stageS((kc + 1) & 1, i0 + 32);
        }
        CP_COMMIT();
        CP_WAIT1();
        if (t < 32) sc[t] = cb[i0 + t];
        __syncthreads();

        // ---- transform: exp + split + transpose into sAh/sAl [j][i] ----
        {
            const float* sSp = (const float*)(dyn + (kc & 1) * AOS_SSZ);
            __half2 hb[8], lb[8];
#pragma unroll
            for (int ii = 0; ii < 16; ii += 2) {
                float s0 = sSp[(ih + ii)     * 132 + jl];
                float s1 = sSp[(ih + ii + 1) * 132 + jl];
                float p0 = __expf(s0 - sc[ih + ii]);
                float p1 = __expf(s1 - sc[ih + ii + 1]);
                __half h0 = __float2half_rn(p0);
                __half h1 = __float2half_rn(p1);
                __half l0 = __float2half_rn(p0 - __half2float(h0));
                __half l1 = __float2half_rn(p1 - __half2float(h1));
                hb[ii >> 1] = __halves2half2(h0, h1);
                lb[ii >> 1] = __halves2half2(l0, l1);
            }
            char* ah = dyn + AOS_AH + jl * PITCH + ih * 2;
            char* al = dyn + AOS_AL + jl * PITCH + ih * 2;
            *(uint4*)(ah)      = *(uint4*)&hb[0];
            *(uint4*)(ah + 16) = *(uint4*)&hb[4];
            *(uint4*)(al)      = *(uint4*)&lb[0];
            *(uint4*)(al + 16) = *(uint4*)&lb[4];
        }
        __syncthreads();

        const uint32_t aoh = su + AOS_AH;
        const uint32_t aol = su + AOS_AL;
        const uint32_t bbh = su + AOS_B0 + (kc & 1) * (2 * OPSZ);
        const uint32_t bbl = bbh + OPSZ;
        K16_STEP(0,  aoh, aol, bbh, bbl);
        K16_STEP(16, aoh, aol, bbh, bbl);
        __syncthreads();
    }

    // ---- epilogue ----
#pragma unroll
    for (int mt = 0; mt < 4; mt++) {
        int row = j0 + wm * 64 + mt * 16 + fr;
#pragma unroll
        for (int nt = 0; nt < 4; nt++) {
            int col = d0 + wn * 32 + nt * 8 + fc;
            float2 v0, v1;
            v0.x = acc[mt][nt][0];
            v0.y = acc[mt][nt][1];
            v1.x = acc[mt][nt][2];
            v1.y = acc[mt][nt][3];
            *(float2*)(Ob + (size_t)row * DD + col)       = v0;
            *(float2*)(Ob + (size_t)(row + 8) * DD + col) = v1;
        }
    }
}

// ---------------------------------------------------------------------------
// V^T build: Vt[b][d][i] = split(Vp[b][i][d])
// ---------------------------------------------------------------------------
__global__ void __launch_bounds__(256)
v_split_t(const float* __restrict__ V,
          __half* __restrict__ Vhi, __half* __restrict__ Vlo)
{
    const int b = blockIdx.z;
    const float* Vb = V + (size_t)b * LL * DD;
    __shared__ float tile[32][33];
    const int tx = threadIdx.x, ty = threadIdx.y;
    const int d0 = blockIdx.x * 32, i0 = blockIdx.y * 32;

#pragma unroll
    for (int r = 0; r < 4; r++) {
        int i = i0 + ty + r * 8;
        tile[ty + r * 8][tx] = Vb[(size_t)i * DD + d0 + tx];
    }
    __syncthreads();
    const size_t ob = (size_t)b * DD * LL;
#pragma unroll
    for (int r = 0; r < 4; r++) {
        int d = d0 + ty + r * 8;
        float v = tile[tx][ty + r * 8];
        __half h, l;
        split_half(v, h, l);
        size_t o = ob + (size_t)d * LL + i0 + tx;
        Vhi[o] = h;
        Vlo[o] = l;
    }
}

// ---------------------------------------------------------------------------
// Launch
// ---------------------------------------------------------------------------
extern "C" void kernel_launch(void* const* d_in, const int* in_sizes, int n_in,
                              void* d_out, int out_size)
{
    const float* q  = (const float*)d_in[0];
    const float* k  = (const float*)d_in[1];
    const float* v  = (const float*)d_in[2];
    const float* Wq = (const float*)d_in[3];
    const float* bq = (const float*)d_in[4];
    const float* Wk = (const float*)d_in[5];
    const float* bk = (const float*)d_in[6];
    const float* Wv = (const float*)d_in[7];
    const float* bv = (const float*)d_in[8];
    float* out = (float*)d_out;

    __half *qhi, *qlo, *khi, *klo, *vthi, *vtlo;
    float *vp, *S, *c, *pm, *ps;
    cudaGetSymbolAddress((void**)&qhi,  g_qhi);
    cudaGetSymbolAddress((void**)&qlo,  g_qlo);
    cudaGetSymbolAddress((void**)&khi,  g_khi);
    cudaGetSymbolAddress((void**)&klo,  g_klo);
    cudaGetSymbolAddress((void**)&vp,   g_vp);
    cudaGetSymbolAddress((void**)&S,    g_S);
    cudaGetSymbolAddress((void**)&c,    g_c);
    cudaGetSymbolAddress((void**)&pm,   g_pm);
    cudaGetSymbolAddress((void**)&ps,   g_ps);
    cudaGetSymbolAddress((void**)&vthi, g_vthi);
    cudaGetSymbolAddress((void**)&vtlo, g_vtlo);

    cudaFuncSetAttribute(score_mma,
                         cudaFuncAttributeMaxDynamicSharedMemorySize, MMA_DYN);
    cudaFuncSetAttribute(attn_out_fused,
                         cudaFuncAttributeMaxDynamicSharedMemorySize, AOS_DYN);

    // 1) Projections (Q,K -> fp16 split; V -> fp32)
    dim3 gProj(DD / TILE, (BB * LL) / TILE, 1);
    gemm_nt<<<gProj, 256>>>(q, Wq, bq, nullptr, qhi, qlo, DD, DD);
    gemm_nt<<<gProj, 256>>>(k, Wk, bk, nullptr, khi, klo, DD, DD);
    gemm_nt<<<gProj, 256>>>(v, Wv, bv, vp, nullptr, nullptr, DD, DD);

    // 2) V^T split
    v_split_t<<<dim3(DD / 32, LL / 32, BB), dim3(32, 8)>>>(vp, vthi, vtlo);

    // 3) Scores + per-tile softmax partials
    score_mma<<<dim3(LL / 128, LL / 128, BB), 256, MMA_DYN>>>(
        qhi, qlo, khi, klo, S, pm, ps, 0.0625f);

    // 4) Combine partials -> c
    combine<<<(BB * LL) / 8, dim3(32, 8)>>>(pm, ps, c);

    // 5) Fused: out[b,j,d] = sum_i exp(S-c) * V'
    attn_out_fused<<<dim3(DD / 128, LL / 128, BB), 256, AOS_DYN>>>(
        S, c, vthi, vtlo, out);
}